// round 13
// baseline (speedup 1.0000x reference)
#include <cuda_runtime.h>
#include <cuda_fp16.h>
#include <math.h>

#define T_TOK 4096
#define D_EMB 1024
#define S_SEQ 2048
#define NH 16
#define HD 64
#define MLP_DIM 4096

// -------- scratch (device globals; no allocation allowed) --------
__device__ __half g_xnh[T_TOK * D_EMB];
__device__ __half g_qh[32 * S_SEQ * HD];
__device__ __half g_kh[32 * S_SEQ * HD];
__device__ __half g_vh[32 * S_SEQ * HD];
__device__ __half g_oh[T_TOK * D_EMB];
__device__ float g_x1[T_TOK * D_EMB];
__device__ __half g_hh[T_TOK * MLP_DIM];
__device__ __half g_W2h[D_EMB * D_EMB];
__device__ float g_b2[D_EMB];
__device__ __half g_wqkvph[D_EMB * 3 * HD * NH];   // [1024][3072]
__device__ __half g_wf1h[D_EMB * MLP_DIM];
__device__ __half g_wf2h[MLP_DIM * D_EMB];

// ---------------- helpers ----------------
__device__ __forceinline__ float geluf(float x) {
    return 0.5f * x * (1.0f + erff(x * 0.70710678118654752f));
}
__device__ __forceinline__ void cpasync16(void* s, const void* g) {
    unsigned sa = (unsigned)__cvta_generic_to_shared(s);
    asm volatile("cp.async.cg.shared.global [%0], [%1], 16;" :: "r"(sa), "l"(g));
}
__device__ __forceinline__ void cpcommit() { asm volatile("cp.async.commit_group;"); }
__device__ __forceinline__ void cpwait0() { asm volatile("cp.async.wait_group 0;"); }
__device__ __forceinline__ void cpwait1() { asm volatile("cp.async.wait_group 1;"); }
__device__ __forceinline__ void mma16h(float* d, const unsigned* a, const unsigned* b) {
    asm volatile(
        "mma.sync.aligned.m16n8k16.row.col.f32.f16.f16.f32 "
        "{%0,%1,%2,%3},{%4,%5,%6,%7},{%8,%9},{%0,%1,%2,%3};"
        : "+f"(d[0]), "+f"(d[1]), "+f"(d[2]), "+f"(d[3])
        : "r"(a[0]), "r"(a[1]), "r"(a[2]), "r"(a[3]), "r"(b[0]), "r"(b[1]));
}
__device__ __forceinline__ void ldsm4(unsigned* r, unsigned addr) {
    asm volatile("ldmatrix.sync.aligned.m8n8.x4.shared.b16 {%0,%1,%2,%3}, [%4];"
        : "=r"(r[0]), "=r"(r[1]), "=r"(r[2]), "=r"(r[3]) : "r"(addr));
}
__device__ __forceinline__ void ldsm4t(unsigned* r, unsigned addr) {
    asm volatile("ldmatrix.sync.aligned.m8n8.x4.trans.shared.b16 {%0,%1,%2,%3}, [%4];"
        : "=r"(r[0]), "=r"(r[1]), "=r"(r[2]), "=r"(r[3]) : "r"(addr));
}

// ---------------- LayerNorm -> half ----------------
__global__ void __launch_bounds__(256) ln_kernel(const float* __restrict__ in,
                                                 const float* __restrict__ g,
                                                 const float* __restrict__ b,
                                                 __half* __restrict__ out) {
    __shared__ float s_sum[256], s_sq[256];
    int row = blockIdx.x, tid = threadIdx.x;
    float4 v = ((const float4*)(in + (size_t)row * D_EMB))[tid];
    s_sum[tid] = v.x + v.y + v.z + v.w;
    s_sq[tid] = v.x * v.x + v.y * v.y + v.z * v.z + v.w * v.w;
    __syncthreads();
    for (int s = 128; s > 0; s >>= 1) {
        if (tid < s) { s_sum[tid] += s_sum[tid + s]; s_sq[tid] += s_sq[tid + s]; }
        __syncthreads();
    }
    float mean = s_sum[0] * (1.0f / D_EMB);
    float var = s_sq[0] * (1.0f / D_EMB) - mean * mean;
    float inv = rsqrtf(var + 1e-5f);
    float4 gg = ((const float4*)g)[tid];
    float4 bb = ((const float4*)b)[tid];
    __half2 h0 = __floats2half2_rn((v.x - mean) * inv * gg.x + bb.x,
                                   (v.y - mean) * inv * gg.y + bb.y);
    __half2 h1 = __floats2half2_rn((v.z - mean) * inv * gg.z + bb.z,
                                   (v.w - mean) * inv * gg.w + bb.w);
    __half2* dst = (__half2*)(out + (size_t)row * D_EMB + tid * 4);
    dst[0] = h0; dst[1] = h1;
}

// ---------------- pack w_qkv [H][D][192] -> [D][H*192], half ----------------
__global__ void __launch_bounds__(256) repack_qkv_kernel(const float* __restrict__ w,
                                                         __half* __restrict__ wp) {
    int i = blockIdx.x * 256 + threadIdx.x;
    int n4 = i % 768, d = i / 768;
    int n = n4 * 4;
    int h = n / 192, f = n - h * 192;
    float4 v = *(const float4*)&w[((size_t)h * D_EMB + d) * 192 + f];
    __half2* dst = (__half2*)&wp[(size_t)d * 3072 + n];
    dst[0] = __floats2half2_rn(v.x, v.y);
    dst[1] = __floats2half2_rn(v.z, v.w);
}

// ---------------- f32 -> f16 for both MLP weights in one launch ----------------
__global__ void __launch_bounds__(256) f2h2_kernel(const float* __restrict__ in1,
                                                   __half* __restrict__ out1,
                                                   const float* __restrict__ in2,
                                                   __half* __restrict__ out2,
                                                   int n4each) {
    int i = blockIdx.x * 256 + threadIdx.x;
    const float* in = (i < n4each) ? in1 : in2;
    __half* out = (i < n4each) ? out1 : out2;
    int j = (i < n4each) ? i : i - n4each;
    float4 v = ((const float4*)in)[j];
    __half2* dst = (__half2*)(out + (size_t)j * 4);
    dst[0] = __floats2half2_rn(v.x, v.y);
    dst[1] = __floats2half2_rn(v.z, v.w);
}

// ---------------- Fuse W2 = blockdiag(w_hproj) @ w_out -> half ----------------
__global__ void __launch_bounds__(256) fuse_w2_kernel(const float* __restrict__ whp,
                                                      const float* __restrict__ wout,
                                                      __half* __restrict__ W2) {
    __shared__ float hp[64 * 64];
    __shared__ float wo[64 * 64];
    int h = blockIdx.x, nt = blockIdx.y, tid = threadIdx.x;
#pragma unroll
    for (int j = 0; j < 4; j++) {
        int f = tid + 256 * j;
        ((float4*)hp)[f] = ((const float4*)(whp + (size_t)h * 4096))[f];
        int r = f >> 4, c4 = f & 15;
        *(float4*)&wo[r * 64 + c4 * 4] =
            *(const float4*)&wout[(size_t)(h * 64 + r) * D_EMB + nt * 64 + c4 * 4];
    }
    __syncthreads();
    int ty = tid >> 4, tx = tid & 15;
#pragma unroll
    for (int i = 0; i < 4; i++) {
        int d = ty * 4 + i;
#pragma unroll
        for (int j = 0; j < 4; j++) {
            int e = tx * 4 + j;
            float acc = 0.f;
#pragma unroll 8
            for (int k = 0; k < 64; k++) acc += hp[d * 64 + k] * wo[k * 64 + e];
            W2[(size_t)(h * 64 + d) * D_EMB + nt * 64 + e] = __float2half_rn(acc);
        }
    }
}

// bias2[e] = b_out[e] + sum_i b_hproj_flat[i] * w_out[i][e]
__global__ void __launch_bounds__(256) bias2_kernel(const float* __restrict__ bhp,
                                                    const float* __restrict__ bout,
                                                    const float* __restrict__ wout,
                                                    float* __restrict__ b2) {
    __shared__ float part[16][16];
    int tid = threadIdx.x;
    int ec = tid & 15;
    int e = blockIdx.x * 16 + ec;
    int chunk = tid >> 4;
    float acc = 0.f;
    int i0 = chunk * 64;
#pragma unroll 8
    for (int i = i0; i < i0 + 64; i++) acc += bhp[i] * wout[(size_t)i * D_EMB + e];
    part[chunk][ec] = acc;
    __syncthreads();
    if (chunk == 0) {
        float s = bout[e];
#pragma unroll
        for (int cch = 0; cch < 16; cch++) s += part[cch][ec];
        b2[e] = s;
    }
}

// ---------------- fp16 tensor-core GEMM 128x128x32, 3-stage, ldmatrix ----------------
#define BM 128
#define BN 128
#define BK 32
#define NSTG 3
#define A_STR 40
#define B_STR 136
#define GEMM_SMEM ((NSTG * (BM * A_STR + BK * B_STR)) * 2)

// EPI 0: qkv scatter -> half, EPI 1: +bias +res -> f32, EPI 2: gelu+bias -> half
template <int EPI>
__global__ void __launch_bounds__(256, 2) gemm_h(
    const __half* __restrict__ A, const __half* __restrict__ B,
    int M, int N, int K,
    const float* __restrict__ bias, const float* __restrict__ res,
    float* __restrict__ outf, __half* __restrict__ outh,
    __half* __restrict__ oq, __half* __restrict__ okk, __half* __restrict__ ov) {
    extern __shared__ __half smh[];
    __half (*As)[BM][A_STR] = (__half (*)[BM][A_STR])smh;
    __half (*Bs)[BK][B_STR] = (__half (*)[BK][B_STR])(smh + NSTG * BM * A_STR);

    int tid = threadIdx.x;
    int lane = tid & 31, warp = tid >> 5;
    int wm = (warp >> 2) * 64, wn = (warp & 3) * 32;
    int bm = blockIdx.x * BM, bn = blockIdx.y * BN;

    float acc[4][4][4];
#pragma unroll
    for (int mi = 0; mi < 4; mi++)
#pragma unroll
        for (int ni = 0; ni < 4; ni++)
#pragma unroll
            for (int q = 0; q < 4; q++) acc[mi][ni][q] = 0.f;

    const __half* Ag = A + (size_t)bm * K;
    const __half* Bg = B + bn;
    int a_row = tid >> 2, a_c8 = (tid & 3) * 8;
    int b_row = tid >> 4, b_c8 = (tid & 15) * 8;

    int T = K / BK;
#pragma unroll
    for (int p = 0; p < NSTG - 1; p++) {
        int k0 = p * BK;
        cpasync16(&As[p][a_row][a_c8], Ag + (size_t)a_row * K + k0 + a_c8);
        cpasync16(&As[p][a_row + 64][a_c8], Ag + (size_t)(a_row + 64) * K + k0 + a_c8);
        cpasync16(&Bs[p][b_row][b_c8], Bg + (size_t)(k0 + b_row) * N + b_c8);
        cpasync16(&Bs[p][b_row + 16][b_c8], Bg + (size_t)(k0 + b_row + 16) * N + b_c8);
        cpcommit();
    }

    int lrow = lane & 15;
    int lhi = (lane >> 4) & 1;
    int r = lane >> 2, c = lane & 3;

    int buf = 0, nstage = NSTG - 1;
    for (int t = 0; t < T; t++) {
        if (t < T - 1) cpwait1(); else cpwait0();
        __syncthreads();
        if (t + 2 < T) {
            int k0 = (t + 2) * BK;
            int s = nstage;
            cpasync16(&As[s][a_row][a_c8], Ag + (size_t)a_row * K + k0 + a_c8);
            cpasync16(&As[s][a_row + 64][a_c8], Ag + (size_t)(a_row + 64) * K + k0 + a_c8);
            cpasync16(&Bs[s][b_row][b_c8], Bg + (size_t)(k0 + b_row) * N + b_c8);
            cpasync16(&Bs[s][b_row + 16][b_c8], Bg + (size_t)(k0 + b_row + 16) * N + b_c8);
            cpcommit();
        }
        nstage = buf;

        unsigned abase = (unsigned)__cvta_generic_to_shared(&As[buf][0][0]);
        unsigned bbase = (unsigned)__cvta_generic_to_shared(&Bs[buf][0][0]);
#pragma unroll
        for (int ks = 0; ks < 2; ks++) {
            int k0 = ks * 16;
            unsigned a[4][4], bq[4][2];
#pragma unroll
            for (int mi = 0; mi < 4; mi++) {
                unsigned ad = abase +
                    (((wm + mi * 16 + lrow) * A_STR) + k0 + lhi * 8) * 2;
                ldsm4(a[mi], ad);
            }
#pragma unroll
            for (int np = 0; np < 2; np++) {
                unsigned tmp[4];
                unsigned bd = bbase +
                    (((k0 + lrow) * B_STR) + wn + np * 16 + lhi * 8) * 2;
                ldsm4t(tmp, bd);
                bq[np * 2][0] = tmp[0]; bq[np * 2][1] = tmp[1];
                bq[np * 2 + 1][0] = tmp[2]; bq[np * 2 + 1][1] = tmp[3];
            }
#pragma unroll
            for (int mi = 0; mi < 4; mi++)
#pragma unroll
                for (int ni = 0; ni < 4; ni++) mma16h(acc[mi][ni], a[mi], bq[ni]);
        }
        buf = (buf + 1 == NSTG) ? 0 : buf + 1;
    }

    int c2 = c * 2;
#pragma unroll
    for (int mi = 0; mi < 4; mi++) {
        int row0 = bm + wm + mi * 16 + r;
        int row1 = row0 + 8;
#pragma unroll
        for (int ni = 0; ni < 4; ni++) {
            int col = bn + wn + ni * 8 + c2;
            float v00 = acc[mi][ni][0], v01 = acc[mi][ni][1];
            float v10 = acc[mi][ni][2], v11 = acc[mi][ni][3];
            if (EPI == 0) {
                int h = col / 192;
                int f = col - h * 192;
                int which = f >> 6;
                int d = f & 63;
                __half* dst = (which == 0) ? oq : (which == 1) ? okk : ov;
                {
                    int b_ = row0 >> 11, s_ = row0 & 2047;
                    size_t base = (((size_t)(b_ * 16 + h) * S_SEQ + s_) * HD + d);
                    *(__half2*)&dst[base] = __floats2half2_rn(v00, v01);
                }
                {
                    int b_ = row1 >> 11, s_ = row1 & 2047;
                    size_t base = (((size_t)(b_ * 16 + h) * S_SEQ + s_) * HD + d);
                    *(__half2*)&dst[base] = __floats2half2_rn(v10, v11);
                }
            } else if (EPI == 1) {
                float2 bv = *(const float2*)&bias[col];
                float2 r0 = *(const float2*)&res[(size_t)row0 * N + col];
                float2 r1 = *(const float2*)&res[(size_t)row1 * N + col];
                float2 o0, o1;
                o0.x = v00 + bv.x + r0.x; o0.y = v01 + bv.y + r0.y;
                o1.x = v10 + bv.x + r1.x; o1.y = v11 + bv.y + r1.y;
                *(float2*)&outf[(size_t)row0 * N + col] = o0;
                *(float2*)&outf[(size_t)row1 * N + col] = o1;
            } else {
                float2 bv = *(const float2*)&bias[col];
                *(__half2*)&outh[(size_t)row0 * N + col] =
                    __floats2half2_rn(geluf(v00 + bv.x), geluf(v01 + bv.y));
                *(__half2*)&outh[(size_t)row1 * N + col] =
                    __floats2half2_rn(geluf(v10 + bv.x), geluf(v11 + bv.y));
            }
        }
    }
}

// ---------------- fp16 flash attention, 128 q-rows / 256 threads / 8 warps ----------------
// Same per-warp 16-row fragment math as the validated 64-row version; K/V tiles
// stay 64 rows double-buffered. Halves K/V global traffic per query row.
#define ATS 72  // half stride (144B rows: ldmatrix-conflict-free)
#define ATT_SMEM_BYTES ((128 * ATS /*Q*/ + 2 * 64 * ATS /*K*/ + 2 * 64 * ATS /*V*/ + 128 * ATS /*P*/) * 2)

__global__ void __launch_bounds__(256) attn_h(const __half* __restrict__ Qg,
                                              const __half* __restrict__ Kg,
                                              const __half* __restrict__ Vg,
                                              __half* __restrict__ Og) {
    extern __shared__ __half smh[];
    __half* Qs = smh;                    // [128][ATS]
    __half* Ks = Qs + 128 * ATS;         // [2][64][ATS]
    __half* Vs = Ks + 2 * 64 * ATS;      // [2][64][ATS]
    __half* Ps = Vs + 2 * 64 * ATS;      // [128][ATS]

    int tid = threadIdx.x, lane = tid & 31, warp = tid >> 5;
    int r = lane >> 2, cq = lane & 3;
    int lrow = lane & 15, lhi = (lane >> 4) & 1;
    int q0 = blockIdx.x * 128, bh = blockIdx.y;
    const __half* qp = Qg + (size_t)bh * S_SEQ * HD;
    const __half* kp = Kg + (size_t)bh * S_SEQ * HD;
    const __half* vp = Vg + (size_t)bh * S_SEQ * HD;

    // prologue: stage Q (128 rows) + K0/V0 (64 rows each) in one group
#pragma unroll
    for (int j = 0; j < 4; j++) {
        int f = tid + 256 * j;
        int row = f >> 3, c8 = (f & 7) * 8;
        cpasync16(&Qs[row * ATS + c8], &qp[(size_t)(q0 + row) * HD + c8]);
    }
#pragma unroll
    for (int j = 0; j < 2; j++) {
        int f = tid + 256 * j;
        int row = f >> 3, c8 = (f & 7) * 8;
        cpasync16(&Ks[row * ATS + c8], &kp[(size_t)row * HD + c8]);
        cpasync16(&Vs[row * ATS + c8], &vp[(size_t)row * HD + c8]);
    }
    cpcommit();

    unsigned qbase = (unsigned)__cvta_generic_to_shared(Qs);
    unsigned pbase = (unsigned)__cvta_generic_to_shared(Ps);
    int qrow = warp * 16 + r;
    int qtile = warp * 16;

    unsigned qa[4][4];
    float m0 = -1e30f, m1 = -1e30f, l0 = 0.f, l1 = 0.f;
    float oacc[8][4];
#pragma unroll
    for (int ni = 0; ni < 8; ni++)
#pragma unroll
        for (int q = 0; q < 4; q++) oacc[ni][q] = 0.f;

    const float scale = 0.125f;
    const int NT = S_SEQ / 64;
    for (int kt = 0; kt < NT; kt++) {
        int buf = kt & 1;
        if (kt + 1 < NT) {
            int nb = 1 - buf;
            const __half* kg = kp + (size_t)(kt + 1) * 64 * HD;
            const __half* vg = vp + (size_t)(kt + 1) * 64 * HD;
            __half* kd = Ks + nb * 64 * ATS;
            __half* vd = Vs + nb * 64 * ATS;
#pragma unroll
            for (int j = 0; j < 2; j++) {
                int f = tid + 256 * j;
                int row = f >> 3, c8 = (f & 7) * 8;
                cpasync16(&kd[row * ATS + c8], &kg[(size_t)row * HD + c8]);
                cpasync16(&vd[row * ATS + c8], &vg[(size_t)row * HD + c8]);
            }
            cpcommit();
            cpwait1();
        } else {
            cpwait0();
        }
        __syncthreads();
        if (kt == 0) {
#pragma unroll
            for (int kf = 0; kf < 4; kf++) {
                unsigned ad = qbase + ((qtile + lrow) * ATS + kf * 16 + lhi * 8) * 2;
                ldsm4(qa[kf], ad);
            }
        }
        unsigned kbase = (unsigned)__cvta_generic_to_shared(Ks + buf * 64 * ATS);
        unsigned vbase = (unsigned)__cvta_generic_to_shared(Vs + buf * 64 * ATS);

        // ---- S = Q @ K^T ----
        float s[8][4];
#pragma unroll
        for (int ni = 0; ni < 8; ni++)
#pragma unroll
            for (int q = 0; q < 4; q++) s[ni][q] = 0.f;
#pragma unroll
        for (int kf = 0; kf < 4; kf++) {
#pragma unroll
            for (int ng = 0; ng < 4; ng++) {
                unsigned tmp[4];
                unsigned kd = kbase + ((ng * 16 + lrow) * ATS + kf * 16 + lhi * 8) * 2;
                ldsm4(tmp, kd);
                unsigned b0[2] = {tmp[0], tmp[2]};
                unsigned b1[2] = {tmp[1], tmp[3]};
                mma16h(s[ng * 2], qa[kf], b0);
                mma16h(s[ng * 2 + 1], qa[kf], b1);
            }
        }

        // ---- online softmax (f32; rows qrow and qrow+8) ----
        float rm0 = -1e30f, rm1 = -1e30f;
#pragma unroll
        for (int ni = 0; ni < 8; ni++) {
            s[ni][0] *= scale; s[ni][1] *= scale;
            s[ni][2] *= scale; s[ni][3] *= scale;
            rm0 = fmaxf(rm0, fmaxf(s[ni][0], s[ni][1]));
            rm1 = fmaxf(rm1, fmaxf(s[ni][2], s[ni][3]));
        }
        rm0 = fmaxf(rm0, __shfl_xor_sync(0xffffffffu, rm0, 1));
        rm0 = fmaxf(rm0, __shfl_xor_sync(0xffffffffu, rm0, 2));
        rm1 = fmaxf(rm1, __shfl_xor_sync(0xffffffffu, rm1, 1));
        rm1 = fmaxf(rm1, __shfl_xor_sync(0xffffffffu, rm1, 2));
        float mn0 = fmaxf(m0, rm0), mn1 = fmaxf(m1, rm1);
        float corr0 = __expf(m0 - mn0), corr1 = __expf(m1 - mn1);
        m0 = mn0; m1 = mn1;
        float rs0 = 0.f, rs1 = 0.f;
#pragma unroll
        for (int ni = 0; ni < 8; ni++) {
            float p0 = __expf(s[ni][0] - mn0);
            float p1 = __expf(s[ni][1] - mn0);
            float p2 = __expf(s[ni][2] - mn1);
            float p3 = __expf(s[ni][3] - mn1);
            rs0 += p0 + p1; rs1 += p2 + p3;
            *(__half2*)&Ps[qrow * ATS + ni * 8 + 2 * cq] = __floats2half2_rn(p0, p1);
            *(__half2*)&Ps[(qrow + 8) * ATS + ni * 8 + 2 * cq] = __floats2half2_rn(p2, p3);
        }
        rs0 += __shfl_xor_sync(0xffffffffu, rs0, 1);
        rs0 += __shfl_xor_sync(0xffffffffu, rs0, 2);
        rs1 += __shfl_xor_sync(0xffffffffu, rs1, 1);
        rs1 += __shfl_xor_sync(0xffffffffu, rs1, 2);
        l0 = l0 * corr0 + rs0;
        l1 = l1 * corr1 + rs1;
#pragma unroll
        for (int ni = 0; ni < 8; ni++) {
            oacc[ni][0] *= corr0; oacc[ni][1] *= corr0;
            oacc[ni][2] *= corr1; oacc[ni][3] *= corr1;
        }
        __syncwarp();  // P rows [warp*16, +16) are warp-private

        // ---- O += P @ V ----
#pragma unroll
        for (int kc = 0; kc < 4; kc++) {
            unsigned pa[4];
            unsigned pd = pbase + ((qtile + lrow) * ATS + kc * 16 + lhi * 8) * 2;
            ldsm4(pa, pd);
#pragma unroll
            for (int ng = 0; ng < 4; ng++) {
                unsigned tmp[4];
                unsigned vd = vbase + ((kc * 16 + lrow) * ATS + ng * 16 + lhi * 8) * 2;
                ldsm4t(tmp, vd);
                unsigned b0[2] = {tmp[0], tmp[1]};
                unsigned b1[2] = {tmp[2], tmp[3]};
                mma16h(oacc[ng * 2], pa, b0);
                mma16h(oacc[ng * 2 + 1], pa, b1);
            }
        }
        __syncthreads();
    }

    // normalize + write concat-head layout as half (feeds proj GEMM A)
    int b_ = bh >> 4, h = bh & 15;
    float inv0 = 1.0f / l0, inv1 = 1.0f / l1;
    size_t t0 = ((size_t)b_ * S_SEQ + q0 + qrow) * D_EMB + h * HD;
    size_t t1 = ((size_t)b_ * S_SEQ + q0 + qrow + 8) * D_EMB + h * HD;
#pragma unroll
    for (int ni = 0; ni < 8; ni++) {
        int d = ni * 8 + 2 * cq;
        *(__half2*)&Og[t0 + d] = __floats2half2_rn(oacc[ni][0] * inv0, oacc[ni][1] * inv0);
        *(__half2*)&Og[t1 + d] = __floats2half2_rn(oacc[ni][2] * inv1, oacc[ni][3] * inv1);
    }
}

// ---------------- launch ----------------
extern "C" void kernel_launch(void* const* d_in, const int* in_sizes, int n_in,
                              void* d_out, int out_size) {
    const float* x = (const float*)d_in[0];
    const float* w_qkv = (const float*)d_in[1];
    const float* w_hproj = (const float*)d_in[2];
    const float* b_hproj = (const float*)d_in[3];
    const float* w_out = (const float*)d_in[4];
    const float* b_out = (const float*)d_in[5];
    const float* w_fc1 = (const float*)d_in[6];
    const float* b_fc1 = (const float*)d_in[7];
    const float* w_fc2 = (const float*)d_in[8];
    const float* b_fc2 = (const float*)d_in[9];
    const float* g1 = (const float*)d_in[10];
    const float* be1 = (const float*)d_in[11];
    const float* g2 = (const float*)d_in[12];
    const float* be2 = (const float*)d_in[13];
    float* out = (float*)d_out;

    __half *xnh, *qh, *kh, *vh, *oh, *hh, *W2h, *wqkvph, *wf1h, *wf2h;
    float *x1, *b2;
    cudaGetSymbolAddress((void**)&xnh, g_xnh);
    cudaGetSymbolAddress((void**)&qh, g_qh);
    cudaGetSymbolAddress((void**)&kh, g_kh);
    cudaGetSymbolAddress((void**)&vh, g_vh);
    cudaGetSymbolAddress((void**)&oh, g_oh);
    cudaGetSymbolAddress((void**)&x1, g_x1);
    cudaGetSymbolAddress((void**)&hh, g_hh);
    cudaGetSymbolAddress((void**)&W2h, g_W2h);
    cudaGetSymbolAddress((void**)&b2, g_b2);
    cudaGetSymbolAddress((void**)&wqkvph, g_wqkvph);
    cudaGetSymbolAddress((void**)&wf1h, g_wf1h);
    cudaGetSymbolAddress((void**)&wf2h, g_wf2h);

    cudaFuncSetAttribute(attn_h, cudaFuncAttributeMaxDynamicSharedMemorySize,
                         ATT_SMEM_BYTES);
    cudaFuncSetAttribute(gemm_h<0>, cudaFuncAttributeMaxDynamicSharedMemorySize, GEMM_SMEM);
    cudaFuncSetAttribute(gemm_h<1>, cudaFuncAttributeMaxDynamicSharedMemorySize, GEMM_SMEM);
    cudaFuncSetAttribute(gemm_h<2>, cudaFuncAttributeMaxDynamicSharedMemorySize, GEMM_SMEM);

    // LN1 + weight prep (independent)
    ln_kernel<<<T_TOK, 256>>>(x, g1, be1, xnh);
    repack_qkv_kernel<<<3072, 256>>>(w_qkv, wqkvph);
    fuse_w2_kernel<<<dim3(16, 16), 256>>>(w_hproj, w_out, W2h);
    bias2_kernel<<<64, 256>>>(b_hproj, b_out, w_out, b2);
    f2h2_kernel<<<8192, 256>>>(w_fc1, wf1h, w_fc2, wf2h, 1024 * 1024);
    // QKV: [4096,1024] x [1024,3072] -> per-head half q/k/v
    gemm_h<0><<<dim3(32, 24), 256, GEMM_SMEM>>>(xnh, wqkvph, T_TOK, 3072, D_EMB,
                                                nullptr, nullptr, nullptr, nullptr,
                                                qh, kh, vh);
    // fp16 flash attention (128-q blocks) -> concat-head half
    attn_h<<<dim3(S_SEQ / 128, 32), 256, ATT_SMEM_BYTES>>>(qh, kh, vh, oh);
    // out projection + bias2 + residual -> x1 (f32)
    gemm_h<1><<<dim3(32, 8), 256, GEMM_SMEM>>>(oh, W2h, T_TOK, D_EMB, D_EMB,
                                               b2, x, x1, nullptr,
                                               nullptr, nullptr, nullptr);
    // LN2
    ln_kernel<<<T_TOK, 256>>>(x1, g2, be2, xnh);
    // FC1 + bias + exact GELU -> half
    gemm_h<2><<<dim3(32, 32), 256, GEMM_SMEM>>>(xnh, wf1h, T_TOK, MLP_DIM, D_EMB,
                                                b_fc1, nullptr, nullptr, hh,
                                                nullptr, nullptr, nullptr);
    // FC2 + bias + residual x1 -> out (f32)
    gemm_h<1><<<dim3(32, 8), 256, GEMM_SMEM>>>(hh, wf2h, T_TOK, D_EMB, MLP_DIM,
                                               b_fc2, x1, out, nullptr,
                                               nullptr, nullptr, nullptr);
}

// round 14
// speedup vs baseline: 1.0091x; 1.0091x over previous
#include <cuda_runtime.h>
#include <cuda_fp16.h>
#include <math.h>

#define T_TOK 4096
#define D_EMB 1024
#define S_SEQ 2048
#define NH 16
#define HD 64
#define MLP_DIM 4096

// -------- scratch (device globals; no allocation allowed) --------
__device__ __half g_xnh[T_TOK * D_EMB];
__device__ __half g_qh[32 * S_SEQ * HD];
__device__ __half g_kh[32 * S_SEQ * HD];
__device__ __half g_vh[32 * S_SEQ * HD];
__device__ __half g_oh[T_TOK * D_EMB];
__device__ float g_x1[T_TOK * D_EMB];
__device__ __half g_hh[T_TOK * MLP_DIM];
__device__ __half g_W2h[D_EMB * D_EMB];
__device__ float g_b2[D_EMB];
__device__ __half g_wqkvph[D_EMB * 3 * HD * NH];   // [1024][3072]
__device__ __half g_wf1h[D_EMB * MLP_DIM];
__device__ __half g_wf2h[MLP_DIM * D_EMB];

// ---------------- helpers ----------------
__device__ __forceinline__ float geluf(float x) {
    return 0.5f * x * (1.0f + erff(x * 0.70710678118654752f));
}
__device__ __forceinline__ void cpasync16(void* s, const void* g) {
    unsigned sa = (unsigned)__cvta_generic_to_shared(s);
    asm volatile("cp.async.cg.shared.global [%0], [%1], 16;" :: "r"(sa), "l"(g));
}
__device__ __forceinline__ void cpcommit() { asm volatile("cp.async.commit_group;"); }
__device__ __forceinline__ void cpwait0() { asm volatile("cp.async.wait_group 0;"); }
__device__ __forceinline__ void cpwait1() { asm volatile("cp.async.wait_group 1;"); }
__device__ __forceinline__ void mma16h(float* d, const unsigned* a, const unsigned* b) {
    asm volatile(
        "mma.sync.aligned.m16n8k16.row.col.f32.f16.f16.f32 "
        "{%0,%1,%2,%3},{%4,%5,%6,%7},{%8,%9},{%0,%1,%2,%3};"
        : "+f"(d[0]), "+f"(d[1]), "+f"(d[2]), "+f"(d[3])
        : "r"(a[0]), "r"(a[1]), "r"(a[2]), "r"(a[3]), "r"(b[0]), "r"(b[1]));
}
__device__ __forceinline__ void ldsm4(unsigned* r, unsigned addr) {
    asm volatile("ldmatrix.sync.aligned.m8n8.x4.shared.b16 {%0,%1,%2,%3}, [%4];"
        : "=r"(r[0]), "=r"(r[1]), "=r"(r[2]), "=r"(r[3]) : "r"(addr));
}
__device__ __forceinline__ void ldsm4t(unsigned* r, unsigned addr) {
    asm volatile("ldmatrix.sync.aligned.m8n8.x4.trans.shared.b16 {%0,%1,%2,%3}, [%4];"
        : "=r"(r[0]), "=r"(r[1]), "=r"(r[2]), "=r"(r[3]) : "r"(addr));
}

// ---------------- LayerNorm -> half (used for LN2; LN1 runs inside prep) ----------------
__device__ __forceinline__ void ln_body(const float* __restrict__ in,
                                        const float* __restrict__ g,
                                        const float* __restrict__ b,
                                        __half* __restrict__ out,
                                        int row, int tid,
                                        float* s_sum, float* s_sq) {
    float4 v = ((const float4*)(in + (size_t)row * D_EMB))[tid];
    s_sum[tid] = v.x + v.y + v.z + v.w;
    s_sq[tid] = v.x * v.x + v.y * v.y + v.z * v.z + v.w * v.w;
    __syncthreads();
    for (int s = 128; s > 0; s >>= 1) {
        if (tid < s) { s_sum[tid] += s_sum[tid + s]; s_sq[tid] += s_sq[tid + s]; }
        __syncthreads();
    }
    float mean = s_sum[0] * (1.0f / D_EMB);
    float var = s_sq[0] * (1.0f / D_EMB) - mean * mean;
    float inv = rsqrtf(var + 1e-5f);
    float4 gg = ((const float4*)g)[tid];
    float4 bb = ((const float4*)b)[tid];
    __half2 h0 = __floats2half2_rn((v.x - mean) * inv * gg.x + bb.x,
                                   (v.y - mean) * inv * gg.y + bb.y);
    __half2 h1 = __floats2half2_rn((v.z - mean) * inv * gg.z + bb.z,
                                   (v.w - mean) * inv * gg.w + bb.w);
    __half2* dst = (__half2*)(out + (size_t)row * D_EMB + tid * 4);
    dst[0] = h0; dst[1] = h1;
}

__global__ void __launch_bounds__(256) ln_kernel(const float* __restrict__ in,
                                                 const float* __restrict__ g,
                                                 const float* __restrict__ b,
                                                 __half* __restrict__ out) {
    __shared__ float s_sum[256], s_sq[256];
    ln_body(in, g, b, out, blockIdx.x, threadIdx.x, s_sum, s_sq);
}

// ---------------- merged prep: LN1 + repack_qkv + f2h(wfc1,wfc2) + fuse_w2 + bias2 ----------------
#define PB_LN 4096
#define PB_RE 3072
#define PB_FH 8192
#define PB_FW 256
#define PB_B2 64
#define PB_TOTAL (PB_LN + PB_RE + PB_FH + PB_FW + PB_B2)
#define PREP_SMEM 32768

__global__ void __launch_bounds__(256) prep_kernel(
    const float* __restrict__ x, const float* __restrict__ g1, const float* __restrict__ be1,
    __half* __restrict__ xnh,
    const float* __restrict__ w_qkv, __half* __restrict__ wqkvph,
    const float* __restrict__ w_fc1, __half* __restrict__ wf1h,
    const float* __restrict__ w_fc2, __half* __restrict__ wf2h,
    const float* __restrict__ whp, const float* __restrict__ wout,
    __half* __restrict__ W2,
    const float* __restrict__ bhp, const float* __restrict__ bout,
    float* __restrict__ b2) {
    extern __shared__ char psm[];
    int blk = blockIdx.x, tid = threadIdx.x;

    if (blk < PB_LN) {
        // ---- LN1 ----
        float* s_sum = (float*)psm;
        float* s_sq = s_sum + 256;
        ln_body(x, g1, be1, xnh, blk, tid, s_sum, s_sq);
        return;
    }
    blk -= PB_LN;
    if (blk < PB_RE) {
        // ---- repack w_qkv [H][D][192] -> [D][3072] half ----
        int i = blk * 256 + tid;
        int n4 = i % 768, d = i / 768;
        int n = n4 * 4;
        int h = n / 192, f = n - h * 192;
        float4 v = *(const float4*)&w_qkv[((size_t)h * D_EMB + d) * 192 + f];
        __half2* dst = (__half2*)&wqkvph[(size_t)d * 3072 + n];
        dst[0] = __floats2half2_rn(v.x, v.y);
        dst[1] = __floats2half2_rn(v.z, v.w);
        return;
    }
    blk -= PB_RE;
    if (blk < PB_FH) {
        // ---- f32 -> f16 for w_fc1 then w_fc2 (1M float4 each) ----
        int i = blk * 256 + tid;
        const int n4each = 1024 * 1024;
        const float* in = (i < n4each) ? w_fc1 : w_fc2;
        __half* out = (i < n4each) ? wf1h : wf2h;
        int j = (i < n4each) ? i : i - n4each;
        float4 v = ((const float4*)in)[j];
        __half2* dst = (__half2*)(out + (size_t)j * 4);
        dst[0] = __floats2half2_rn(v.x, v.y);
        dst[1] = __floats2half2_rn(v.z, v.w);
        return;
    }
    blk -= PB_FH;
    if (blk < PB_FW) {
        // ---- fuse W2 = blockdiag(w_hproj) @ w_out -> half ----
        float* hp = (float*)psm;          // 64*64
        float* wo = hp + 4096;            // 64*64
        int h = blk & 15, nt = blk >> 4;
#pragma unroll
        for (int j = 0; j < 4; j++) {
            int f = tid + 256 * j;
            ((float4*)hp)[f] = ((const float4*)(whp + (size_t)h * 4096))[f];
            int r = f >> 4, c4 = f & 15;
            *(float4*)&wo[r * 64 + c4 * 4] =
                *(const float4*)&wout[(size_t)(h * 64 + r) * D_EMB + nt * 64 + c4 * 4];
        }
        __syncthreads();
        int ty = tid >> 4, tx = tid & 15;
#pragma unroll
        for (int i = 0; i < 4; i++) {
            int d = ty * 4 + i;
#pragma unroll
            for (int j = 0; j < 4; j++) {
                int e = tx * 4 + j;
                float acc = 0.f;
#pragma unroll 8
                for (int k = 0; k < 64; k++) acc += hp[d * 64 + k] * wo[k * 64 + e];
                W2[(size_t)(h * 64 + d) * D_EMB + nt * 64 + e] = __float2half_rn(acc);
            }
        }
        return;
    }
    blk -= PB_FW;
    {
        // ---- bias2[e] = b_out[e] + sum_i b_hproj_flat[i] * w_out[i][e] ----
        float (*part)[16] = (float (*)[16])psm;
        int ec = tid & 15;
        int e = blk * 16 + ec;
        int chunk = tid >> 4;
        float acc = 0.f;
        int i0 = chunk * 64;
#pragma unroll 8
        for (int i = i0; i < i0 + 64; i++) acc += bhp[i] * wout[(size_t)i * D_EMB + e];
        part[chunk][ec] = acc;
        __syncthreads();
        if (chunk == 0) {
            float s = bout[e];
#pragma unroll
            for (int cch = 0; cch < 16; cch++) s += part[cch][ec];
            b2[e] = s;
        }
    }
}

// ---------------- fp16 tensor-core GEMM 128x128x32, 3-stage, ldmatrix ----------------
#define BM 128
#define BN 128
#define BK 32
#define NSTG 3
#define A_STR 40
#define B_STR 136
#define GEMM_SMEM ((NSTG * (BM * A_STR + BK * B_STR)) * 2)

// EPI 0: qkv scatter -> half, EPI 1: +bias +res -> f32, EPI 2: gelu+bias -> half
template <int EPI>
__global__ void __launch_bounds__(256, 2) gemm_h(
    const __half* __restrict__ A, const __half* __restrict__ B,
    int M, int N, int K,
    const float* __restrict__ bias, const float* __restrict__ res,
    float* __restrict__ outf, __half* __restrict__ outh,
    __half* __restrict__ oq, __half* __restrict__ okk, __half* __restrict__ ov) {
    extern __shared__ __half smh[];
    __half (*As)[BM][A_STR] = (__half (*)[BM][A_STR])smh;
    __half (*Bs)[BK][B_STR] = (__half (*)[BK][B_STR])(smh + NSTG * BM * A_STR);

    int tid = threadIdx.x;
    int lane = tid & 31, warp = tid >> 5;
    int wm = (warp >> 2) * 64, wn = (warp & 3) * 32;
    int bm = blockIdx.x * BM, bn = blockIdx.y * BN;

    float acc[4][4][4];
#pragma unroll
    for (int mi = 0; mi < 4; mi++)
#pragma unroll
        for (int ni = 0; ni < 4; ni++)
#pragma unroll
            for (int q = 0; q < 4; q++) acc[mi][ni][q] = 0.f;

    const __half* Ag = A + (size_t)bm * K;
    const __half* Bg = B + bn;
    int a_row = tid >> 2, a_c8 = (tid & 3) * 8;
    int b_row = tid >> 4, b_c8 = (tid & 15) * 8;

    int T = K / BK;
#pragma unroll
    for (int p = 0; p < NSTG - 1; p++) {
        int k0 = p * BK;
        cpasync16(&As[p][a_row][a_c8], Ag + (size_t)a_row * K + k0 + a_c8);
        cpasync16(&As[p][a_row + 64][a_c8], Ag + (size_t)(a_row + 64) * K + k0 + a_c8);
        cpasync16(&Bs[p][b_row][b_c8], Bg + (size_t)(k0 + b_row) * N + b_c8);
        cpasync16(&Bs[p][b_row + 16][b_c8], Bg + (size_t)(k0 + b_row + 16) * N + b_c8);
        cpcommit();
    }

    int lrow = lane & 15;
    int lhi = (lane >> 4) & 1;
    int r = lane >> 2, c = lane & 3;

    int buf = 0, nstage = NSTG - 1;
    for (int t = 0; t < T; t++) {
        if (t < T - 1) cpwait1(); else cpwait0();
        __syncthreads();
        if (t + 2 < T) {
            int k0 = (t + 2) * BK;
            int s = nstage;
            cpasync16(&As[s][a_row][a_c8], Ag + (size_t)a_row * K + k0 + a_c8);
            cpasync16(&As[s][a_row + 64][a_c8], Ag + (size_t)(a_row + 64) * K + k0 + a_c8);
            cpasync16(&Bs[s][b_row][b_c8], Bg + (size_t)(k0 + b_row) * N + b_c8);
            cpasync16(&Bs[s][b_row + 16][b_c8], Bg + (size_t)(k0 + b_row + 16) * N + b_c8);
            cpcommit();
        }
        nstage = buf;

        unsigned abase = (unsigned)__cvta_generic_to_shared(&As[buf][0][0]);
        unsigned bbase = (unsigned)__cvta_generic_to_shared(&Bs[buf][0][0]);
#pragma unroll
        for (int ks = 0; ks < 2; ks++) {
            int k0 = ks * 16;
            unsigned a[4][4], bq[4][2];
#pragma unroll
            for (int mi = 0; mi < 4; mi++) {
                unsigned ad = abase +
                    (((wm + mi * 16 + lrow) * A_STR) + k0 + lhi * 8) * 2;
                ldsm4(a[mi], ad);
            }
#pragma unroll
            for (int np = 0; np < 2; np++) {
                unsigned tmp[4];
                unsigned bd = bbase +
                    (((k0 + lrow) * B_STR) + wn + np * 16 + lhi * 8) * 2;
                ldsm4t(tmp, bd);
                bq[np * 2][0] = tmp[0]; bq[np * 2][1] = tmp[1];
                bq[np * 2 + 1][0] = tmp[2]; bq[np * 2 + 1][1] = tmp[3];
            }
#pragma unroll
            for (int mi = 0; mi < 4; mi++)
#pragma unroll
                for (int ni = 0; ni < 4; ni++) mma16h(acc[mi][ni], a[mi], bq[ni]);
        }
        buf = (buf + 1 == NSTG) ? 0 : buf + 1;
    }

    int c2 = c * 2;
#pragma unroll
    for (int mi = 0; mi < 4; mi++) {
        int row0 = bm + wm + mi * 16 + r;
        int row1 = row0 + 8;
#pragma unroll
        for (int ni = 0; ni < 4; ni++) {
            int col = bn + wn + ni * 8 + c2;
            float v00 = acc[mi][ni][0], v01 = acc[mi][ni][1];
            float v10 = acc[mi][ni][2], v11 = acc[mi][ni][3];
            if (EPI == 0) {
                int h = col / 192;
                int f = col - h * 192;
                int which = f >> 6;
                int d = f & 63;
                __half* dst = (which == 0) ? oq : (which == 1) ? okk : ov;
                {
                    int b_ = row0 >> 11, s_ = row0 & 2047;
                    size_t base = (((size_t)(b_ * 16 + h) * S_SEQ + s_) * HD + d);
                    *(__half2*)&dst[base] = __floats2half2_rn(v00, v01);
                }
                {
                    int b_ = row1 >> 11, s_ = row1 & 2047;
                    size_t base = (((size_t)(b_ * 16 + h) * S_SEQ + s_) * HD + d);
                    *(__half2*)&dst[base] = __floats2half2_rn(v10, v11);
                }
            } else if (EPI == 1) {
                float2 bv = *(const float2*)&bias[col];
                float2 r0 = *(const float2*)&res[(size_t)row0 * N + col];
                float2 r1 = *(const float2*)&res[(size_t)row1 * N + col];
                float2 o0, o1;
                o0.x = v00 + bv.x + r0.x; o0.y = v01 + bv.y + r0.y;
                o1.x = v10 + bv.x + r1.x; o1.y = v11 + bv.y + r1.y;
                *(float2*)&outf[(size_t)row0 * N + col] = o0;
                *(float2*)&outf[(size_t)row1 * N + col] = o1;
            } else {
                float2 bv = *(const float2*)&bias[col];
                *(__half2*)&outh[(size_t)row0 * N + col] =
                    __floats2half2_rn(geluf(v00 + bv.x), geluf(v01 + bv.y));
                *(__half2*)&outh[(size_t)row1 * N + col] =
                    __floats2half2_rn(geluf(v10 + bv.x), geluf(v11 + bv.y));
            }
        }
    }
}

// ---------------- fp16 tensor-core flash attention (R7-validated: 64 q-rows) ----------------
#define ATS 72
#define ATT_SMEM_BYTES ((64 * ATS + 2 * 64 * ATS + 2 * 64 * ATS + 64 * ATS) * 2)

__global__ void __launch_bounds__(128) attn_h(const __half* __restrict__ Qg,
                                              const __half* __restrict__ Kg,
                                              const __half* __restrict__ Vg,
                                              __half* __restrict__ Og) {
    extern __shared__ __half smh[];
    __half* Qs = smh;
    __half* Ks = Qs + 64 * ATS;
    __half* Vs = Ks + 2 * 64 * ATS;
    __half* Ps = Vs + 2 * 64 * ATS;

    int tid = threadIdx.x, lane = tid & 31, warp = tid >> 5;
    int r = lane >> 2, cq = lane & 3;
    int lrow = lane & 15, lhi = (lane >> 4) & 1;
    int q0 = blockIdx.x * 64, bh = blockIdx.y;
    const __half* qp = Qg + (size_t)bh * S_SEQ * HD;
    const __half* kp = Kg + (size_t)bh * S_SEQ * HD;
    const __half* vp = Vg + (size_t)bh * S_SEQ * HD;

#pragma unroll
    for (int j = 0; j < 4; j++) {
        int f = tid + 128 * j;
        int row = f >> 3, c8 = (f & 7) * 8;
        cpasync16(&Qs[row * ATS + c8], &qp[(size_t)(q0 + row) * HD + c8]);
        cpasync16(&Ks[row * ATS + c8], &kp[(size_t)row * HD + c8]);
        cpasync16(&Vs[row * ATS + c8], &vp[(size_t)row * HD + c8]);
    }
    cpcommit();

    unsigned qbase = (unsigned)__cvta_generic_to_shared(Qs);
    unsigned pbase = (unsigned)__cvta_generic_to_shared(Ps);
    int qrow = warp * 16 + r;
    int qtile = warp * 16;

    unsigned qa[4][4];
    float m0 = -1e30f, m1 = -1e30f, l0 = 0.f, l1 = 0.f;
    float oacc[8][4];
#pragma unroll
    for (int ni = 0; ni < 8; ni++)
#pragma unroll
        for (int q = 0; q < 4; q++) oacc[ni][q] = 0.f;

    const float scale = 0.125f;
    const int NT = S_SEQ / 64;
    for (int kt = 0; kt < NT; kt++) {
        int buf = kt & 1;
        if (kt + 1 < NT) {
            int nb = 1 - buf;
            const __half* kg = kp + (size_t)(kt + 1) * 64 * HD;
            const __half* vg = vp + (size_t)(kt + 1) * 64 * HD;
            __half* kd = Ks + nb * 64 * ATS;
            __half* vd = Vs + nb * 64 * ATS;
#pragma unroll
            for (int j = 0; j < 4; j++) {
                int f = tid + 128 * j;
                int row = f >> 3, c8 = (f & 7) * 8;
                cpasync16(&kd[row * ATS + c8], &kg[(size_t)row * HD + c8]);
                cpasync16(&vd[row * ATS + c8], &vg[(size_t)row * HD + c8]);
            }
            cpcommit();
            cpwait1();
        } else {
            cpwait0();
        }
        __syncthreads();
        if (kt == 0) {
#pragma unroll
            for (int kf = 0; kf < 4; kf++) {
                unsigned ad = qbase + ((qtile + lrow) * ATS + kf * 16 + lhi * 8) * 2;
                ldsm4(qa[kf], ad);
            }
        }
        unsigned kbase = (unsigned)__cvta_generic_to_shared(Ks + buf * 64 * ATS);
        unsigned vbase = (unsigned)__cvta_generic_to_shared(Vs + buf * 64 * ATS);

        float s[8][4];
#pragma unroll
        for (int ni = 0; ni < 8; ni++)
#pragma unroll
            for (int q = 0; q < 4; q++) s[ni][q] = 0.f;
#pragma unroll
        for (int kf = 0; kf < 4; kf++) {
#pragma unroll
            for (int ng = 0; ng < 4; ng++) {
                unsigned tmp[4];
                unsigned kd = kbase + ((ng * 16 + lrow) * ATS + kf * 16 + lhi * 8) * 2;
                ldsm4(tmp, kd);
                unsigned b0[2] = {tmp[0], tmp[2]};
                unsigned b1[2] = {tmp[1], tmp[3]};
                mma16h(s[ng * 2], qa[kf], b0);
                mma16h(s[ng * 2 + 1], qa[kf], b1);
            }
        }

        float rm0 = -1e30f, rm1 = -1e30f;
#pragma unroll
        for (int ni = 0; ni < 8; ni++) {
            s[ni][0] *= scale; s[ni][1] *= scale;
            s[ni][2] *= scale; s[ni][3] *= scale;
            rm0 = fmaxf(rm0, fmaxf(s[ni][0], s[ni][1]));
            rm1 = fmaxf(rm1, fmaxf(s[ni][2], s[ni][3]));
        }
        rm0 = fmaxf(rm0, __shfl_xor_sync(0xffffffffu, rm0, 1));
        rm0 = fmaxf(rm0, __shfl_xor_sync(0xffffffffu, rm0, 2));
        rm1 = fmaxf(rm1, __shfl_xor_sync(0xffffffffu, rm1, 1));
        rm1 = fmaxf(rm1, __shfl_xor_sync(0xffffffffu, rm1, 2));
        float mn0 = fmaxf(m0, rm0), mn1 = fmaxf(m1, rm1);
        float corr0 = __expf(m0 - mn0), corr1 = __expf(m1 - mn1);
        m0 = mn0; m1 = mn1;
        float rs0 = 0.f, rs1 = 0.f;
#pragma unroll
        for (int ni = 0; ni < 8; ni++) {
            float p0 = __expf(s[ni][0] - mn0);
            float p1 = __expf(s[ni][1] - mn0);
            float p2 = __expf(s[ni][2] - mn1);
            float p3 = __expf(s[ni][3] - mn1);
            rs0 += p0 + p1; rs1 += p2 + p3;
            *(__half2*)&Ps[qrow * ATS + ni * 8 + 2 * cq] = __floats2half2_rn(p0, p1);
            *(__half2*)&Ps[(qrow + 8) * ATS + ni * 8 + 2 * cq] = __floats2half2_rn(p2, p3);
        }
        rs0 += __shfl_xor_sync(0xffffffffu, rs0, 1);
        rs0 += __shfl_xor_sync(0xffffffffu, rs0, 2);
        rs1 += __shfl_xor_sync(0xffffffffu, rs1, 1);
        rs1 += __shfl_xor_sync(0xffffffffu, rs1, 2);
        l0 = l0 * corr0 + rs0;
        l1 = l1 * corr1 + rs1;
#pragma unroll
        for (int ni = 0; ni < 8; ni++) {
            oacc[ni][0] *= corr0; oacc[ni][1] *= corr0;
            oacc[ni][2] *= corr1; oacc[ni][3] *= corr1;
        }
        __syncwarp();

#pragma unroll
        for (int kc = 0; kc < 4; kc++) {
            unsigned pa[4];
            unsigned pd = pbase + ((qtile + lrow) * ATS + kc * 16 + lhi * 8) * 2;
            ldsm4(pa, pd);
#pragma unroll
            for (int ng = 0; ng < 4; ng++) {
                unsigned tmp[4];
                unsigned vd = vbase + ((kc * 16 + lrow) * ATS + ng * 16 + lhi * 8) * 2;
                ldsm4t(tmp, vd);
                unsigned b0[2] = {tmp[0], tmp[1]};
                unsigned b1[2] = {tmp[2], tmp[3]};
                mma16h(oacc[ng * 2], pa, b0);
                mma16h(oacc[ng * 2 + 1], pa, b1);
            }
        }
        __syncthreads();
    }

    int b_ = bh >> 4, h = bh & 15;
    float inv0 = 1.0f / l0, inv1 = 1.0f / l1;
    size_t t0 = ((size_t)b_ * S_SEQ + q0 + qrow) * D_EMB + h * HD;
    size_t t1 = ((size_t)b_ * S_SEQ + q0 + qrow + 8) * D_EMB + h * HD;
#pragma unroll
    for (int ni = 0; ni < 8; ni++) {
        int d = ni * 8 + 2 * cq;
        *(__half2*)&Og[t0 + d] = __floats2half2_rn(oacc[ni][0] * inv0, oacc[ni][1] * inv0);
        *(__half2*)&Og[t1 + d] = __floats2half2_rn(oacc[ni][2] * inv1, oacc[ni][3] * inv1);
    }
}

// ---------------- launch ----------------
extern "C" void kernel_launch(void* const* d_in, const int* in_sizes, int n_in,
                              void* d_out, int out_size) {
    const float* x = (const float*)d_in[0];
    const float* w_qkv = (const float*)d_in[1];
    const float* w_hproj = (const float*)d_in[2];
    const float* b_hproj = (const float*)d_in[3];
    const float* w_out = (const float*)d_in[4];
    const float* b_out = (const float*)d_in[5];
    const float* w_fc1 = (const float*)d_in[6];
    const float* b_fc1 = (const float*)d_in[7];
    const float* w_fc2 = (const float*)d_in[8];
    const float* b_fc2 = (const float*)d_in[9];
    const float* g1 = (const float*)d_in[10];
    const float* be1 = (const float*)d_in[11];
    const float* g2 = (const float*)d_in[12];
    const float* be2 = (const float*)d_in[13];
    float* out = (float*)d_out;

    __half *xnh, *qh, *kh, *vh, *oh, *hh, *W2h, *wqkvph, *wf1h, *wf2h;
    float *x1, *b2;
    cudaGetSymbolAddress((void**)&xnh, g_xnh);
    cudaGetSymbolAddress((void**)&qh, g_qh);
    cudaGetSymbolAddress((void**)&kh, g_kh);
    cudaGetSymbolAddress((void**)&vh, g_vh);
    cudaGetSymbolAddress((void**)&oh, g_oh);
    cudaGetSymbolAddress((void**)&x1, g_x1);
    cudaGetSymbolAddress((void**)&hh, g_hh);
    cudaGetSymbolAddress((void**)&W2h, g_W2h);
    cudaGetSymbolAddress((void**)&b2, g_b2);
    cudaGetSymbolAddress((void**)&wqkvph, g_wqkvph);
    cudaGetSymbolAddress((void**)&wf1h, g_wf1h);
    cudaGetSymbolAddress((void**)&wf2h, g_wf2h);

    cudaFuncSetAttribute(attn_h, cudaFuncAttributeMaxDynamicSharedMemorySize,
                         ATT_SMEM_BYTES);
    cudaFuncSetAttribute(gemm_h<0>, cudaFuncAttributeMaxDynamicSharedMemorySize, GEMM_SMEM);
    cudaFuncSetAttribute(gemm_h<1>, cudaFuncAttributeMaxDynamicSharedMemorySize, GEMM_SMEM);
    cudaFuncSetAttribute(gemm_h<2>, cudaFuncAttributeMaxDynamicSharedMemorySize, GEMM_SMEM);

    // merged LN1 + all weight prep in ONE launch (branches overlap on-chip)
    prep_kernel<<<PB_TOTAL, 256, PREP_SMEM>>>(
        x, g1, be1, xnh,
        w_qkv, wqkvph,
        w_fc1, wf1h, w_fc2, wf2h,
        w_hproj, w_out, W2h,
        b_hproj, b_out, b2);
    // QKV: [4096,1024] x [1024,3072] -> per-head half q/k/v
    gemm_h<0><<<dim3(32, 24), 256, GEMM_SMEM>>>(xnh, wqkvph, T_TOK, 3072, D_EMB,
                                                nullptr, nullptr, nullptr, nullptr,
                                                qh, kh, vh);
    // fp16 flash attention -> concat-head half
    attn_h<<<dim3(S_SEQ / 64, 32), 128, ATT_SMEM_BYTES>>>(qh, kh, vh, oh);
    // out projection + bias2 + residual -> x1 (f32)
    gemm_h<1><<<dim3(32, 8), 256, GEMM_SMEM>>>(oh, W2h, T_TOK, D_EMB, D_EMB,
                                               b2, x, x1, nullptr,
                                               nullptr, nullptr, nullptr);
    // LN2
    ln_kernel<<<T_TOK, 256>>>(x1, g2, be2, xnh);
    // FC1 + bias + exact GELU -> half
    gemm_h<2><<<dim3(32, 32), 256, GEMM_SMEM>>>(xnh, wf1h, T_TOK, MLP_DIM, D_EMB,
                                                b_fc1, nullptr, nullptr, hh,
                                                nullptr, nullptr, nullptr);
    // FC2 + bias + residual x1 -> out (f32)
    gemm_h<1><<<dim3(32, 8), 256, GEMM_SMEM>>>(hh, wf2h, T_TOK, D_EMB, MLP_DIM,
                                               b_fc2, x1, out, nullptr,
                                               nullptr, nullptr, nullptr);
}

// round 15
// speedup vs baseline: 1.0454x; 1.0360x over previous
#include <cuda_runtime.h>
#include <cuda_fp16.h>
#include <math.h>

#define T_TOK 4096
#define D_EMB 1024
#define S_SEQ 2048
#define NH 16
#define HD 64
#define MLP_DIM 4096

// -------- scratch (device globals; no allocation allowed) --------
__device__ __half g_xnh[T_TOK * D_EMB];
__device__ __half g_qh[32 * S_SEQ * HD];
__device__ __half g_kh[32 * S_SEQ * HD];
__device__ __half g_vh[32 * S_SEQ * HD];
__device__ __half g_oh[T_TOK * D_EMB];
__device__ float g_x1[T_TOK * D_EMB];
__device__ __half g_hh[T_TOK * MLP_DIM];
__device__ __half g_W2h[D_EMB * D_EMB];
__device__ float g_b2p[4 * D_EMB];                 // bias2 partials (4 quarters)
__device__ __half g_wqkvph[D_EMB * 3 * HD * NH];   // [1024][3072]
__device__ __half g_wf1h[D_EMB * MLP_DIM];
__device__ __half g_wf2h[MLP_DIM * D_EMB];

// ---------------- helpers ----------------
__device__ __forceinline__ float geluf(float x) {
    return 0.5f * x * (1.0f + erff(x * 0.70710678118654752f));
}
__device__ __forceinline__ void cpasync16(void* s, const void* g) {
    unsigned sa = (unsigned)__cvta_generic_to_shared(s);
    asm volatile("cp.async.cg.shared.global [%0], [%1], 16;" :: "r"(sa), "l"(g));
}
__device__ __forceinline__ void cpcommit() { asm volatile("cp.async.commit_group;"); }
__device__ __forceinline__ void cpwait0() { asm volatile("cp.async.wait_group 0;"); }
__device__ __forceinline__ void cpwait1() { asm volatile("cp.async.wait_group 1;"); }
__device__ __forceinline__ void mma16h(float* d, const unsigned* a, const unsigned* b) {
    asm volatile(
        "mma.sync.aligned.m16n8k16.row.col.f32.f16.f16.f32 "
        "{%0,%1,%2,%3},{%4,%5,%6,%7},{%8,%9},{%0,%1,%2,%3};"
        : "+f"(d[0]), "+f"(d[1]), "+f"(d[2]), "+f"(d[3])
        : "r"(a[0]), "r"(a[1]), "r"(a[2]), "r"(a[3]), "r"(b[0]), "r"(b[1]));
}
__device__ __forceinline__ void ldsm4(unsigned* r, unsigned addr) {
    asm volatile("ldmatrix.sync.aligned.m8n8.x4.shared.b16 {%0,%1,%2,%3}, [%4];"
        : "=r"(r[0]), "=r"(r[1]), "=r"(r[2]), "=r"(r[3]) : "r"(addr));
}
__device__ __forceinline__ void ldsm4t(unsigned* r, unsigned addr) {
    asm volatile("ldmatrix.sync.aligned.m8n8.x4.trans.shared.b16 {%0,%1,%2,%3}, [%4];"
        : "=r"(r[0]), "=r"(r[1]), "=r"(r[2]), "=r"(r[3]) : "r"(addr));
}

// ---------------- LayerNorm -> half (warp-shuffle reduction, 2 barriers) ----------------
__global__ void __launch_bounds__(256) ln_kernel(const float* __restrict__ in,
                                                 const float* __restrict__ g,
                                                 const float* __restrict__ b,
                                                 __half* __restrict__ out) {
    __shared__ float sw[8][2];
    __shared__ float sres[2];
    int row = blockIdx.x, tid = threadIdx.x;
    int warp = tid >> 5, lane = tid & 31;
    float4 v = ((const float4*)(in + (size_t)row * D_EMB))[tid];
    float sum = v.x + v.y + v.z + v.w;
    float sq = v.x * v.x + v.y * v.y + v.z * v.z + v.w * v.w;
#pragma unroll
    for (int off = 16; off >= 1; off >>= 1) {
        sum += __shfl_xor_sync(0xffffffffu, sum, off);
        sq += __shfl_xor_sync(0xffffffffu, sq, off);
    }
    if (lane == 0) { sw[warp][0] = sum; sw[warp][1] = sq; }
    __syncthreads();
    if (warp == 0) {
        float s = (lane < 8) ? sw[lane][0] : 0.f;
        float q = (lane < 8) ? sw[lane][1] : 0.f;
#pragma unroll
        for (int off = 4; off >= 1; off >>= 1) {
            s += __shfl_xor_sync(0xffffffffu, s, off);
            q += __shfl_xor_sync(0xffffffffu, q, off);
        }
        if (lane == 0) { sres[0] = s; sres[1] = q; }
    }
    __syncthreads();
    float mean = sres[0] * (1.0f / D_EMB);
    float var = sres[1] * (1.0f / D_EMB) - mean * mean;
    float inv = rsqrtf(var + 1e-5f);
    float4 gg = ((const float4*)g)[tid];
    float4 bb = ((const float4*)b)[tid];
    __half2 h0 = __floats2half2_rn((v.x - mean) * inv * gg.x + bb.x,
                                   (v.y - mean) * inv * gg.y + bb.y);
    __half2 h1 = __floats2half2_rn((v.z - mean) * inv * gg.z + bb.z,
                                   (v.w - mean) * inv * gg.w + bb.w);
    __half2* dst = (__half2*)(out + (size_t)row * D_EMB + tid * 4);
    dst[0] = h0; dst[1] = h1;
}

// ---------------- pack w_qkv [H][D][192] -> [D][H*192], half ----------------
__global__ void __launch_bounds__(256) repack_qkv_kernel(const float* __restrict__ w,
                                                         __half* __restrict__ wp) {
    int i = blockIdx.x * 256 + threadIdx.x;
    int n4 = i % 768, d = i / 768;
    int n = n4 * 4;
    int h = n / 192, f = n - h * 192;
    float4 v = *(const float4*)&w[((size_t)h * D_EMB + d) * 192 + f];
    __half2* dst = (__half2*)&wp[(size_t)d * 3072 + n];
    dst[0] = __floats2half2_rn(v.x, v.y);
    dst[1] = __floats2half2_rn(v.z, v.w);
}

// ---------------- f32 -> f16 for both MLP weights in one launch ----------------
__global__ void __launch_bounds__(256) f2h2_kernel(const float* __restrict__ in1,
                                                   __half* __restrict__ out1,
                                                   const float* __restrict__ in2,
                                                   __half* __restrict__ out2,
                                                   int n4each) {
    int i = blockIdx.x * 256 + threadIdx.x;
    const float* in = (i < n4each) ? in1 : in2;
    __half* out = (i < n4each) ? out1 : out2;
    int j = (i < n4each) ? i : i - n4each;
    float4 v = ((const float4*)in)[j];
    __half2* dst = (__half2*)(out + (size_t)j * 4);
    dst[0] = __floats2half2_rn(v.x, v.y);
    dst[1] = __floats2half2_rn(v.z, v.w);
}

// ---------------- Fuse W2 = blockdiag(w_hproj) @ w_out -> half ----------------
__global__ void __launch_bounds__(256) fuse_w2_kernel(const float* __restrict__ whp,
                                                      const float* __restrict__ wout,
                                                      __half* __restrict__ W2) {
    __shared__ float hp[64 * 64];
    __shared__ float wo[64 * 64];
    int h = blockIdx.x, nt = blockIdx.y, tid = threadIdx.x;
#pragma unroll
    for (int j = 0; j < 4; j++) {
        int f = tid + 256 * j;
        ((float4*)hp)[f] = ((const float4*)(whp + (size_t)h * 4096))[f];
        int r = f >> 4, c4 = f & 15;
        *(float4*)&wo[r * 64 + c4 * 4] =
            *(const float4*)&wout[(size_t)(h * 64 + r) * D_EMB + nt * 64 + c4 * 4];
    }
    __syncthreads();
    int ty = tid >> 4, tx = tid & 15;
#pragma unroll
    for (int i = 0; i < 4; i++) {
        int d = ty * 4 + i;
#pragma unroll
        for (int j = 0; j < 4; j++) {
            int e = tx * 4 + j;
            float acc = 0.f;
#pragma unroll 8
            for (int k = 0; k < 64; k++) acc += hp[d * 64 + k] * wo[k * 64 + e];
            W2[(size_t)(h * 64 + d) * D_EMB + nt * 64 + e] = __float2half_rn(acc);
        }
    }
}

// bias2 partials: b2p[iq][e] = sum_{i in quarter iq} bhp[i] * wout[i][e]
// 256 blocks (64 e-chunks x 4 i-quarters); final bout+sum folded into proj epilogue.
__global__ void __launch_bounds__(256) bias2p_kernel(const float* __restrict__ bhp,
                                                     const float* __restrict__ wout,
                                                     float* __restrict__ b2p) {
    __shared__ float part[16][16];
    int blk = blockIdx.x, tid = threadIdx.x;
    int ec = blk & 63, iq = blk >> 6;
    int e = ec * 16 + (tid & 15);
    int chunk = tid >> 4;
    float acc = 0.f;
    int i0 = iq * 256 + chunk * 16;
#pragma unroll
    for (int i = i0; i < i0 + 16; i++) acc += bhp[i] * wout[(size_t)i * D_EMB + e];
    part[chunk][tid & 15] = acc;
    __syncthreads();
    if (chunk == 0) {
        float s = 0.f;
#pragma unroll
        for (int cch = 0; cch < 16; cch++) s += part[cch][tid & 15];
        b2p[iq * D_EMB + e] = s;
    }
}

// ---------------- fp16 tensor-core GEMM 128x128x32, 3-stage, ldmatrix ----------------
#define BM 128
#define BN 128
#define BK 32
#define NSTG 3
#define A_STR 40
#define B_STR 136
#define GEMM_SMEM ((NSTG * (BM * A_STR + BK * B_STR)) * 2)

// EPI 0: qkv scatter -> half, EPI 1: +bias +res -> f32,
// EPI 2: gelu+bias -> half, EPI 3: +bias +4 b2p partials +res -> f32
template <int EPI>
__global__ void __launch_bounds__(256, 2) gemm_h(
    const __half* __restrict__ A, const __half* __restrict__ B,
    int M, int N, int K,
    const float* __restrict__ bias, const float* __restrict__ res,
    const float* __restrict__ b2p,
    float* __restrict__ outf, __half* __restrict__ outh,
    __half* __restrict__ oq, __half* __restrict__ okk, __half* __restrict__ ov) {
    extern __shared__ __half smh[];
    __half (*As)[BM][A_STR] = (__half (*)[BM][A_STR])smh;
    __half (*Bs)[BK][B_STR] = (__half (*)[BK][B_STR])(smh + NSTG * BM * A_STR);

    int tid = threadIdx.x;
    int lane = tid & 31, warp = tid >> 5;
    int wm = (warp >> 2) * 64, wn = (warp & 3) * 32;
    int bm = blockIdx.x * BM, bn = blockIdx.y * BN;

    float acc[4][4][4];
#pragma unroll
    for (int mi = 0; mi < 4; mi++)
#pragma unroll
        for (int ni = 0; ni < 4; ni++)
#pragma unroll
            for (int q = 0; q < 4; q++) acc[mi][ni][q] = 0.f;

    const __half* Ag = A + (size_t)bm * K;
    const __half* Bg = B + bn;
    int a_row = tid >> 2, a_c8 = (tid & 3) * 8;
    int b_row = tid >> 4, b_c8 = (tid & 15) * 8;

    int T = K / BK;
#pragma unroll
    for (int p = 0; p < NSTG - 1; p++) {
        int k0 = p * BK;
        cpasync16(&As[p][a_row][a_c8], Ag + (size_t)a_row * K + k0 + a_c8);
        cpasync16(&As[p][a_row + 64][a_c8], Ag + (size_t)(a_row + 64) * K + k0 + a_c8);
        cpasync16(&Bs[p][b_row][b_c8], Bg + (size_t)(k0 + b_row) * N + b_c8);
        cpasync16(&Bs[p][b_row + 16][b_c8], Bg + (size_t)(k0 + b_row + 16) * N + b_c8);
        cpcommit();
    }

    int lrow = lane & 15;
    int lhi = (lane >> 4) & 1;
    int r = lane >> 2, c = lane & 3;

    int buf = 0, nstage = NSTG - 1;
    for (int t = 0; t < T; t++) {
        if (t < T - 1) cpwait1(); else cpwait0();
        __syncthreads();
        if (t + 2 < T) {
            int k0 = (t + 2) * BK;
            int s = nstage;
            cpasync16(&As[s][a_row][a_c8], Ag + (size_t)a_row * K + k0 + a_c8);
            cpasync16(&As[s][a_row + 64][a_c8], Ag + (size_t)(a_row + 64) * K + k0 + a_c8);
            cpasync16(&Bs[s][b_row][b_c8], Bg + (size_t)(k0 + b_row) * N + b_c8);
            cpasync16(&Bs[s][b_row + 16][b_c8], Bg + (size_t)(k0 + b_row + 16) * N + b_c8);
            cpcommit();
        }
        nstage = buf;

        unsigned abase = (unsigned)__cvta_generic_to_shared(&As[buf][0][0]);
        unsigned bbase = (unsigned)__cvta_generic_to_shared(&Bs[buf][0][0]);
#pragma unroll
        for (int ks = 0; ks < 2; ks++) {
            int k0 = ks * 16;
            unsigned a[4][4], bq[4][2];
#pragma unroll
            for (int mi = 0; mi < 4; mi++) {
                unsigned ad = abase +
                    (((wm + mi * 16 + lrow) * A_STR) + k0 + lhi * 8) * 2;
                ldsm4(a[mi], ad);
            }
#pragma unroll
            for (int np = 0; np < 2; np++) {
                unsigned tmp[4];
                unsigned bd = bbase +
                    (((k0 + lrow) * B_STR) + wn + np * 16 + lhi * 8) * 2;
                ldsm4t(tmp, bd);
                bq[np * 2][0] = tmp[0]; bq[np * 2][1] = tmp[1];
                bq[np * 2 + 1][0] = tmp[2]; bq[np * 2 + 1][1] = tmp[3];
            }
#pragma unroll
            for (int mi = 0; mi < 4; mi++)
#pragma unroll
                for (int ni = 0; ni < 4; ni++) mma16h(acc[mi][ni], a[mi], bq[ni]);
        }
        buf = (buf + 1 == NSTG) ? 0 : buf + 1;
    }

    int c2 = c * 2;
#pragma unroll
    for (int mi = 0; mi < 4; mi++) {
        int row0 = bm + wm + mi * 16 + r;
        int row1 = row0 + 8;
#pragma unroll
        for (int ni = 0; ni < 4; ni++) {
            int col = bn + wn + ni * 8 + c2;
            float v00 = acc[mi][ni][0], v01 = acc[mi][ni][1];
            float v10 = acc[mi][ni][2], v11 = acc[mi][ni][3];
            if (EPI == 0) {
                int h = col / 192;
                int f = col - h * 192;
                int which = f >> 6;
                int d = f & 63;
                __half* dst = (which == 0) ? oq : (which == 1) ? okk : ov;
                {
                    int b_ = row0 >> 11, s_ = row0 & 2047;
                    size_t base = (((size_t)(b_ * 16 + h) * S_SEQ + s_) * HD + d);
                    *(__half2*)&dst[base] = __floats2half2_rn(v00, v01);
                }
                {
                    int b_ = row1 >> 11, s_ = row1 & 2047;
                    size_t base = (((size_t)(b_ * 16 + h) * S_SEQ + s_) * HD + d);
                    *(__half2*)&dst[base] = __floats2half2_rn(v10, v11);
                }
            } else if (EPI == 1) {
                float2 bv = *(const float2*)&bias[col];
                float2 r0 = *(const float2*)&res[(size_t)row0 * N + col];
                float2 r1 = *(const float2*)&res[(size_t)row1 * N + col];
                float2 o0, o1;
                o0.x = v00 + bv.x + r0.x; o0.y = v01 + bv.y + r0.y;
                o1.x = v10 + bv.x + r1.x; o1.y = v11 + bv.y + r1.y;
                *(float2*)&outf[(size_t)row0 * N + col] = o0;
                *(float2*)&outf[(size_t)row1 * N + col] = o1;
            } else if (EPI == 3) {
                float2 bv = *(const float2*)&bias[col];
                float2 p0 = *(const float2*)&b2p[col];
                float2 p1 = *(const float2*)&b2p[D_EMB + col];
                float2 p2 = *(const float2*)&b2p[2 * D_EMB + col];
                float2 p3 = *(const float2*)&b2p[3 * D_EMB + col];
                float bx = bv.x + p0.x + p1.x + p2.x + p3.x;
                float by = bv.y + p0.y + p1.y + p2.y + p3.y;
                float2 r0 = *(const float2*)&res[(size_t)row0 * N + col];
                float2 r1 = *(const float2*)&res[(size_t)row1 * N + col];
                float2 o0, o1;
                o0.x = v00 + bx + r0.x; o0.y = v01 + by + r0.y;
                o1.x = v10 + bx + r1.x; o1.y = v11 + by + r1.y;
                *(float2*)&outf[(size_t)row0 * N + col] = o0;
                *(float2*)&outf[(size_t)row1 * N + col] = o1;
            } else {
                float2 bv = *(const float2*)&bias[col];
                *(__half2*)&outh[(size_t)row0 * N + col] =
                    __floats2half2_rn(geluf(v00 + bv.x), geluf(v01 + bv.y));
                *(__half2*)&outh[(size_t)row1 * N + col] =
                    __floats2half2_rn(geluf(v10 + bv.x), geluf(v11 + bv.y));
            }
        }
    }
}

// ---------------- fp16 tensor-core flash attention (R7-validated: 64 q-rows) ----------------
#define ATS 72
#define ATT_SMEM_BYTES ((64 * ATS + 2 * 64 * ATS + 2 * 64 * ATS + 64 * ATS) * 2)

__global__ void __launch_bounds__(128) attn_h(const __half* __restrict__ Qg,
                                              const __half* __restrict__ Kg,
                                              const __half* __restrict__ Vg,
                                              __half* __restrict__ Og) {
    extern __shared__ __half smh[];
    __half* Qs = smh;
    __half* Ks = Qs + 64 * ATS;
    __half* Vs = Ks + 2 * 64 * ATS;
    __half* Ps = Vs + 2 * 64 * ATS;

    int tid = threadIdx.x, lane = tid & 31, warp = tid >> 5;
    int r = lane >> 2, cq = lane & 3;
    int lrow = lane & 15, lhi = (lane >> 4) & 1;
    int q0 = blockIdx.x * 64, bh = blockIdx.y;
    const __half* qp = Qg + (size_t)bh * S_SEQ * HD;
    const __half* kp = Kg + (size_t)bh * S_SEQ * HD;
    const __half* vp = Vg + (size_t)bh * S_SEQ * HD;

#pragma unroll
    for (int j = 0; j < 4; j++) {
        int f = tid + 128 * j;
        int row = f >> 3, c8 = (f & 7) * 8;
        cpasync16(&Qs[row * ATS + c8], &qp[(size_t)(q0 + row) * HD + c8]);
        cpasync16(&Ks[row * ATS + c8], &kp[(size_t)row * HD + c8]);
        cpasync16(&Vs[row * ATS + c8], &vp[(size_t)row * HD + c8]);
    }
    cpcommit();

    unsigned qbase = (unsigned)__cvta_generic_to_shared(Qs);
    unsigned pbase = (unsigned)__cvta_generic_to_shared(Ps);
    int qrow = warp * 16 + r;
    int qtile = warp * 16;

    unsigned qa[4][4];
    float m0 = -1e30f, m1 = -1e30f, l0 = 0.f, l1 = 0.f;
    float oacc[8][4];
#pragma unroll
    for (int ni = 0; ni < 8; ni++)
#pragma unroll
        for (int q = 0; q < 4; q++) oacc[ni][q] = 0.f;

    const float scale = 0.125f;
    const int NT = S_SEQ / 64;
    for (int kt = 0; kt < NT; kt++) {
        int buf = kt & 1;
        if (kt + 1 < NT) {
            int nb = 1 - buf;
            const __half* kg = kp + (size_t)(kt + 1) * 64 * HD;
            const __half* vg = vp + (size_t)(kt + 1) * 64 * HD;
            __half* kd = Ks + nb * 64 * ATS;
            __half* vd = Vs + nb * 64 * ATS;
#pragma unroll
            for (int j = 0; j < 4; j++) {
                int f = tid + 128 * j;
                int row = f >> 3, c8 = (f & 7) * 8;
                cpasync16(&kd[row * ATS + c8], &kg[(size_t)row * HD + c8]);
                cpasync16(&vd[row * ATS + c8], &vg[(size_t)row * HD + c8]);
            }
            cpcommit();
            cpwait1();
        } else {
            cpwait0();
        }
        __syncthreads();
        if (kt == 0) {
#pragma unroll
            for (int kf = 0; kf < 4; kf++) {
                unsigned ad = qbase + ((qtile + lrow) * ATS + kf * 16 + lhi * 8) * 2;
                ldsm4(qa[kf], ad);
            }
        }
        unsigned kbase = (unsigned)__cvta_generic_to_shared(Ks + buf * 64 * ATS);
        unsigned vbase = (unsigned)__cvta_generic_to_shared(Vs + buf * 64 * ATS);

        float s[8][4];
#pragma unroll
        for (int ni = 0; ni < 8; ni++)
#pragma unroll
            for (int q = 0; q < 4; q++) s[ni][q] = 0.f;
#pragma unroll
        for (int kf = 0; kf < 4; kf++) {
#pragma unroll
            for (int ng = 0; ng < 4; ng++) {
                unsigned tmp[4];
                unsigned kd = kbase + ((ng * 16 + lrow) * ATS + kf * 16 + lhi * 8) * 2;
                ldsm4(tmp, kd);
                unsigned b0[2] = {tmp[0], tmp[2]};
                unsigned b1[2] = {tmp[1], tmp[3]};
                mma16h(s[ng * 2], qa[kf], b0);
                mma16h(s[ng * 2 + 1], qa[kf], b1);
            }
        }

        float rm0 = -1e30f, rm1 = -1e30f;
#pragma unroll
        for (int ni = 0; ni < 8; ni++) {
            s[ni][0] *= scale; s[ni][1] *= scale;
            s[ni][2] *= scale; s[ni][3] *= scale;
            rm0 = fmaxf(rm0, fmaxf(s[ni][0], s[ni][1]));
            rm1 = fmaxf(rm1, fmaxf(s[ni][2], s[ni][3]));
        }
        rm0 = fmaxf(rm0, __shfl_xor_sync(0xffffffffu, rm0, 1));
        rm0 = fmaxf(rm0, __shfl_xor_sync(0xffffffffu, rm0, 2));
        rm1 = fmaxf(rm1, __shfl_xor_sync(0xffffffffu, rm1, 1));
        rm1 = fmaxf(rm1, __shfl_xor_sync(0xffffffffu, rm1, 2));
        float mn0 = fmaxf(m0, rm0), mn1 = fmaxf(m1, rm1);
        float corr0 = __expf(m0 - mn0), corr1 = __expf(m1 - mn1);
        m0 = mn0; m1 = mn1;
        float rs0 = 0.f, rs1 = 0.f;
#pragma unroll
        for (int ni = 0; ni < 8; ni++) {
            float p0 = __expf(s[ni][0] - mn0);
            float p1 = __expf(s[ni][1] - mn0);
            float p2 = __expf(s[ni][2] - mn1);
            float p3 = __expf(s[ni][3] - mn1);
            rs0 += p0 + p1; rs1 += p2 + p3;
            *(__half2*)&Ps[qrow * ATS + ni * 8 + 2 * cq] = __floats2half2_rn(p0, p1);
            *(__half2*)&Ps[(qrow + 8) * ATS + ni * 8 + 2 * cq] = __floats2half2_rn(p2, p3);
        }
        rs0 += __shfl_xor_sync(0xffffffffu, rs0, 1);
        rs0 += __shfl_xor_sync(0xffffffffu, rs0, 2);
        rs1 += __shfl_xor_sync(0xffffffffu, rs1, 1);
        rs1 += __shfl_xor_sync(0xffffffffu, rs1, 2);
        l0 = l0 * corr0 + rs0;
        l1 = l1 * corr1 + rs1;
#pragma unroll
        for (int ni = 0; ni < 8; ni++) {
            oacc[ni][0] *= corr0; oacc[ni][1] *= corr0;
            oacc[ni][2] *= corr1; oacc[ni][3] *= corr1;
        }
        __syncwarp();

#pragma unroll
        for (int kc = 0; kc < 4; kc++) {
            unsigned pa[4];
            unsigned pd = pbase + ((qtile + lrow) * ATS + kc * 16 + lhi * 8) * 2;
            ldsm4(pa, pd);
#pragma unroll
            for (int ng = 0; ng < 4; ng++) {
                unsigned tmp[4];
                unsigned vd = vbase + ((kc * 16 + lrow) * ATS + ng * 16 + lhi * 8) * 2;
                ldsm4t(tmp, vd);
                unsigned b0[2] = {tmp[0], tmp[1]};
                unsigned b1[2] = {tmp[2], tmp[3]};
                mma16h(oacc[ng * 2], pa, b0);
                mma16h(oacc[ng * 2 + 1], pa, b1);
            }
        }
        __syncthreads();
    }

    int b_ = bh >> 4, h = bh & 15;
    float inv0 = 1.0f / l0, inv1 = 1.0f / l1;
    size_t t0 = ((size_t)b_ * S_SEQ + q0 + qrow) * D_EMB + h * HD;
    size_t t1 = ((size_t)b_ * S_SEQ + q0 + qrow + 8) * D_EMB + h * HD;
#pragma unroll
    for (int ni = 0; ni < 8; ni++) {
        int d = ni * 8 + 2 * cq;
        *(__half2*)&Og[t0 + d] = __floats2half2_rn(oacc[ni][0] * inv0, oacc[ni][1] * inv0);
        *(__half2*)&Og[t1 + d] = __floats2half2_rn(oacc[ni][2] * inv1, oacc[ni][3] * inv1);
    }
}

// ---------------- launch ----------------
extern "C" void kernel_launch(void* const* d_in, const int* in_sizes, int n_in,
                              void* d_out, int out_size) {
    const float* x = (const float*)d_in[0];
    const float* w_qkv = (const float*)d_in[1];
    const float* w_hproj = (const float*)d_in[2];
    const float* b_hproj = (const float*)d_in[3];
    const float* w_out = (const float*)d_in[4];
    const float* b_out = (const float*)d_in[5];
    const float* w_fc1 = (const float*)d_in[6];
    const float* b_fc1 = (const float*)d_in[7];
    const float* w_fc2 = (const float*)d_in[8];
    const float* b_fc2 = (const float*)d_in[9];
    const float* g1 = (const float*)d_in[10];
    const float* be1 = (const float*)d_in[11];
    const float* g2 = (const float*)d_in[12];
    const float* be2 = (const float*)d_in[13];
    float* out = (float*)d_out;

    __half *xnh, *qh, *kh, *vh, *oh, *hh, *W2h, *wqkvph, *wf1h, *wf2h;
    float *x1, *b2p;
    cudaGetSymbolAddress((void**)&xnh, g_xnh);
    cudaGetSymbolAddress((void**)&qh, g_qh);
    cudaGetSymbolAddress((void**)&kh, g_kh);
    cudaGetSymbolAddress((void**)&vh, g_vh);
    cudaGetSymbolAddress((void**)&oh, g_oh);
    cudaGetSymbolAddress((void**)&x1, g_x1);
    cudaGetSymbolAddress((void**)&hh, g_hh);
    cudaGetSymbolAddress((void**)&W2h, g_W2h);
    cudaGetSymbolAddress((void**)&b2p, g_b2p);
    cudaGetSymbolAddress((void**)&wqkvph, g_wqkvph);
    cudaGetSymbolAddress((void**)&wf1h, g_wf1h);
    cudaGetSymbolAddress((void**)&wf2h, g_wf2h);

    cudaFuncSetAttribute(attn_h, cudaFuncAttributeMaxDynamicSharedMemorySize,
                         ATT_SMEM_BYTES);
    cudaFuncSetAttribute(gemm_h<0>, cudaFuncAttributeMaxDynamicSharedMemorySize, GEMM_SMEM);
    cudaFuncSetAttribute(gemm_h<1>, cudaFuncAttributeMaxDynamicSharedMemorySize, GEMM_SMEM);
    cudaFuncSetAttribute(gemm_h<2>, cudaFuncAttributeMaxDynamicSharedMemorySize, GEMM_SMEM);
    cudaFuncSetAttribute(gemm_h<3>, cudaFuncAttributeMaxDynamicSharedMemorySize, GEMM_SMEM);

    // LN1 + weight prep (separate small launches — measured faster than merged)
    ln_kernel<<<T_TOK, 256>>>(x, g1, be1, xnh);
    repack_qkv_kernel<<<3072, 256>>>(w_qkv, wqkvph);
    fuse_w2_kernel<<<dim3(16, 16), 256>>>(w_hproj, w_out, W2h);
    bias2p_kernel<<<256, 256>>>(b_hproj, w_out, b2p);
    f2h2_kernel<<<8192, 256>>>(w_fc1, wf1h, w_fc2, wf2h, 1024 * 1024);
    // QKV: [4096,1024] x [1024,3072] -> per-head half q/k/v
    gemm_h<0><<<dim3(32, 24), 256, GEMM_SMEM>>>(xnh, wqkvph, T_TOK, 3072, D_EMB,
                                                nullptr, nullptr, nullptr, nullptr, nullptr,
                                                qh, kh, vh);
    // fp16 flash attention -> concat-head half
    attn_h<<<dim3(S_SEQ / 64, 32), 128, ATT_SMEM_BYTES>>>(qh, kh, vh, oh);
    // out projection + (bout + b2 partials) + residual -> x1 (f32)
    gemm_h<3><<<dim3(32, 8), 256, GEMM_SMEM>>>(oh, W2h, T_TOK, D_EMB, D_EMB,
                                               b_out, x, b2p, x1, nullptr,
                                               nullptr, nullptr, nullptr);
    // LN2
    ln_kernel<<<T_TOK, 256>>>(x1, g2, be2, xnh);
    // FC1 + bias + exact GELU -> half
    gemm_h<2><<<dim3(32, 32), 256, GEMM_SMEM>>>(xnh, wf1h, T_TOK, MLP_DIM, D_EMB,
                                                b_fc1, nullptr, nullptr, nullptr, hh,
                                                nullptr, nullptr, nullptr);
    // FC2 + bias + residual x1 -> out (f32)
    gemm_h<1><<<dim3(32, 8), 256, GEMM_SMEM>>>(hh, wf2h, T_TOK, D_EMB, MLP_DIM,
                                               b_fc2, x1, nullptr, out, nullptr,
                                               nullptr, nullptr, nullptr);
}

// round 16
// speedup vs baseline: 1.1200x; 1.0714x over previous
#include <cuda_runtime.h>
#include <cuda_fp16.h>
#include <math.h>

#define T_TOK 4096
#define D_EMB 1024
#define S_SEQ 2048
#define NH 16
#define HD 64
#define MLP_DIM 4096

// -------- scratch (device globals; no allocation allowed) --------
__device__ __half g_xnh[T_TOK * D_EMB];
__device__ __half g_qh[32 * S_SEQ * HD];
__device__ __half g_kh[32 * S_SEQ * HD];
__device__ __half g_vh[32 * S_SEQ * HD];
__device__ __half g_oh[T_TOK * D_EMB];
__device__ float g_x1[T_TOK * D_EMB];
__device__ __half g_hh[T_TOK * MLP_DIM];
__device__ __half g_W2h[D_EMB * D_EMB];
__device__ float g_b2p[4 * D_EMB];                 // bias2 partials (4 quarters)
__device__ __half g_wqkvph[D_EMB * 3 * HD * NH];   // [1024][3072]
__device__ __half g_wf1h[D_EMB * MLP_DIM];
__device__ __half g_wf2h[MLP_DIM * D_EMB];

// ---------------- helpers ----------------
__device__ __forceinline__ float geluf(float x) {
    return 0.5f * x * (1.0f + erff(x * 0.70710678118654752f));
}
__device__ __forceinline__ void cpasync16(void* s, const void* g) {
    unsigned sa = (unsigned)__cvta_generic_to_shared(s);
    asm volatile("cp.async.cg.shared.global [%0], [%1], 16;" :: "r"(sa), "l"(g));
}
__device__ __forceinline__ void cpcommit() { asm volatile("cp.async.commit_group;"); }
__device__ __forceinline__ void cpwait0() { asm volatile("cp.async.wait_group 0;"); }
__device__ __forceinline__ void cpwait1() { asm volatile("cp.async.wait_group 1;"); }
__device__ __forceinline__ void mma16h(float* d, const unsigned* a, const unsigned* b) {
    asm volatile(
        "mma.sync.aligned.m16n8k16.row.col.f32.f16.f16.f32 "
        "{%0,%1,%2,%3},{%4,%5,%6,%7},{%8,%9},{%0,%1,%2,%3};"
        : "+f"(d[0]), "+f"(d[1]), "+f"(d[2]), "+f"(d[3])
        : "r"(a[0]), "r"(a[1]), "r"(a[2]), "r"(a[3]), "r"(b[0]), "r"(b[1]));
}
__device__ __forceinline__ void ldsm4(unsigned* r, unsigned addr) {
    asm volatile("ldmatrix.sync.aligned.m8n8.x4.shared.b16 {%0,%1,%2,%3}, [%4];"
        : "=r"(r[0]), "=r"(r[1]), "=r"(r[2]), "=r"(r[3]) : "r"(addr));
}
__device__ __forceinline__ void ldsm4t(unsigned* r, unsigned addr) {
    asm volatile("ldmatrix.sync.aligned.m8n8.x4.trans.shared.b16 {%0,%1,%2,%3}, [%4];"
        : "=r"(r[0]), "=r"(r[1]), "=r"(r[2]), "=r"(r[3]) : "r"(addr));
}

// ---------------- LayerNorm -> half (warp-shuffle reduction, 2 barriers) ----------------
__global__ void __launch_bounds__(256) ln_kernel(const float* __restrict__ in,
                                                 const float* __restrict__ g,
                                                 const float* __restrict__ b,
                                                 __half* __restrict__ out) {
    __shared__ float sw[8][2];
    __shared__ float sres[2];
    int row = blockIdx.x, tid = threadIdx.x;
    int warp = tid >> 5, lane = tid & 31;
    float4 v = ((const float4*)(in + (size_t)row * D_EMB))[tid];
    float sum = v.x + v.y + v.z + v.w;
    float sq = v.x * v.x + v.y * v.y + v.z * v.z + v.w * v.w;
#pragma unroll
    for (int off = 16; off >= 1; off >>= 1) {
        sum += __shfl_xor_sync(0xffffffffu, sum, off);
        sq += __shfl_xor_sync(0xffffffffu, sq, off);
    }
    if (lane == 0) { sw[warp][0] = sum; sw[warp][1] = sq; }
    __syncthreads();
    if (warp == 0) {
        float s = (lane < 8) ? sw[lane][0] : 0.f;
        float q = (lane < 8) ? sw[lane][1] : 0.f;
#pragma unroll
        for (int off = 4; off >= 1; off >>= 1) {
            s += __shfl_xor_sync(0xffffffffu, s, off);
            q += __shfl_xor_sync(0xffffffffu, q, off);
        }
        if (lane == 0) { sres[0] = s; sres[1] = q; }
    }
    __syncthreads();
    float mean = sres[0] * (1.0f / D_EMB);
    float var = sres[1] * (1.0f / D_EMB) - mean * mean;
    float inv = rsqrtf(var + 1e-5f);
    float4 gg = ((const float4*)g)[tid];
    float4 bb = ((const float4*)b)[tid];
    __half2 h0 = __floats2half2_rn((v.x - mean) * inv * gg.x + bb.x,
                                   (v.y - mean) * inv * gg.y + bb.y);
    __half2 h1 = __floats2half2_rn((v.z - mean) * inv * gg.z + bb.z,
                                   (v.w - mean) * inv * gg.w + bb.w);
    __half2* dst = (__half2*)(out + (size_t)row * D_EMB + tid * 4);
    dst[0] = h0; dst[1] = h1;
}

// ---------------- pack w_qkv [H][D][192] -> [D][H*192], half ----------------
__global__ void __launch_bounds__(256) repack_qkv_kernel(const float* __restrict__ w,
                                                         __half* __restrict__ wp) {
    int i = blockIdx.x * 256 + threadIdx.x;
    int n4 = i % 768, d = i / 768;
    int n = n4 * 4;
    int h = n / 192, f = n - h * 192;
    float4 v = *(const float4*)&w[((size_t)h * D_EMB + d) * 192 + f];
    __half2* dst = (__half2*)&wp[(size_t)d * 3072 + n];
    dst[0] = __floats2half2_rn(v.x, v.y);
    dst[1] = __floats2half2_rn(v.z, v.w);
}

// ---------------- f32 -> f16 for both MLP weights in one launch ----------------
__global__ void __launch_bounds__(256) f2h2_kernel(const float* __restrict__ in1,
                                                   __half* __restrict__ out1,
                                                   const float* __restrict__ in2,
                                                   __half* __restrict__ out2,
                                                   int n4each) {
    int i = blockIdx.x * 256 + threadIdx.x;
    const float* in = (i < n4each) ? in1 : in2;
    __half* out = (i < n4each) ? out1 : out2;
    int j = (i < n4each) ? i : i - n4each;
    float4 v = ((const float4*)in)[j];
    __half2* dst = (__half2*)(out + (size_t)j * 4);
    dst[0] = __floats2half2_rn(v.x, v.y);
    dst[1] = __floats2half2_rn(v.z, v.w);
}

// ---------------- Fuse W2 = blockdiag(w_hproj) @ w_out -> half ----------------
__global__ void __launch_bounds__(256) fuse_w2_kernel(const float* __restrict__ whp,
                                                      const float* __restrict__ wout,
                                                      __half* __restrict__ W2) {
    __shared__ float hp[64 * 64];
    __shared__ float wo[64 * 64];
    int h = blockIdx.x, nt = blockIdx.y, tid = threadIdx.x;
#pragma unroll
    for (int j = 0; j < 4; j++) {
        int f = tid + 256 * j;
        ((float4*)hp)[f] = ((const float4*)(whp + (size_t)h * 4096))[f];
        int r = f >> 4, c4 = f & 15;
        *(float4*)&wo[r * 64 + c4 * 4] =
            *(const float4*)&wout[(size_t)(h * 64 + r) * D_EMB + nt * 64 + c4 * 4];
    }
    __syncthreads();
    int ty = tid >> 4, tx = tid & 15;
#pragma unroll
    for (int i = 0; i < 4; i++) {
        int d = ty * 4 + i;
#pragma unroll
        for (int j = 0; j < 4; j++) {
            int e = tx * 4 + j;
            float acc = 0.f;
#pragma unroll 8
            for (int k = 0; k < 64; k++) acc += hp[d * 64 + k] * wo[k * 64 + e];
            W2[(size_t)(h * 64 + d) * D_EMB + nt * 64 + e] = __float2half_rn(acc);
        }
    }
}

// bias2 partials: b2p[iq][e] = sum_{i in quarter iq} bhp[i] * wout[i][e]
__global__ void __launch_bounds__(256) bias2p_kernel(const float* __restrict__ bhp,
                                                     const float* __restrict__ wout,
                                                     float* __restrict__ b2p) {
    __shared__ float part[16][16];
    int blk = blockIdx.x, tid = threadIdx.x;
    int ec = blk & 63, iq = blk >> 6;
    int e = ec * 16 + (tid & 15);
    int chunk = tid >> 4;
    float acc = 0.f;
    int i0 = iq * 256 + chunk * 16;
#pragma unroll
    for (int i = i0; i < i0 + 16; i++) acc += bhp[i] * wout[(size_t)i * D_EMB + e];
    part[chunk][tid & 15] = acc;
    __syncthreads();
    if (chunk == 0) {
        float s = 0.f;
#pragma unroll
        for (int cch = 0; cch < 16; cch++) s += part[cch][tid & 15];
        b2p[iq * D_EMB + e] = s;
    }
}

// ---------------- fp16 tensor-core GEMM 128x128x64, 2-stage, ldmatrix ----------------
#define BM 128
#define BN 128
#define BK 64
#define NSTG 2
#define A_STR 72     // 64 + 8 halfs pad (144B rows: ldmatrix conflict-free, same as attn)
#define B_STR 136    // 128 + 8 halfs pad
#define GEMM_SMEM ((NSTG * (BM * A_STR + BK * B_STR)) * 2)

// EPI 0: qkv scatter -> half, EPI 1: +bias +res -> f32,
// EPI 2: gelu+bias -> half, EPI 3: +bias +4 b2p partials +res -> f32
template <int EPI>
__global__ void __launch_bounds__(256, 2) gemm_h(
    const __half* __restrict__ A, const __half* __restrict__ B,
    int M, int N, int K,
    const float* __restrict__ bias, const float* __restrict__ res,
    const float* __restrict__ b2p,
    float* __restrict__ outf, __half* __restrict__ outh,
    __half* __restrict__ oq, __half* __restrict__ okk, __half* __restrict__ ov) {
    extern __shared__ __half smh[];
    __half (*As)[BM][A_STR] = (__half (*)[BM][A_STR])smh;
    __half (*Bs)[BK][B_STR] = (__half (*)[BK][B_STR])(smh + NSTG * BM * A_STR);

    int tid = threadIdx.x;
    int lane = tid & 31, warp = tid >> 5;
    int wm = (warp >> 2) * 64, wn = (warp & 3) * 32;
    int bm = blockIdx.x * BM, bn = blockIdx.y * BN;

    float acc[4][4][4];
#pragma unroll
    for (int mi = 0; mi < 4; mi++)
#pragma unroll
        for (int ni = 0; ni < 4; ni++)
#pragma unroll
            for (int q = 0; q < 4; q++) acc[mi][ni][q] = 0.f;

    const __half* Ag = A + (size_t)bm * K;
    const __half* Bg = B + bn;
    // A tile: 128 x 64h = 1024 16B-chunks; 4/thread. idx>>3 = row, (idx&7)*8 = col.
    // B tile: 64 x 128h = 1024 chunks; idx>>4 = row, (idx&15)*8 = col.
    int T = K / BK;

    {
#pragma unroll
        for (int j = 0; j < 4; j++) {
            int idx = tid + 256 * j;
            int ar = idx >> 3, ac = (idx & 7) * 8;
            cpasync16(&As[0][ar][ac], Ag + (size_t)ar * K + ac);
            int br = idx >> 4, bc = (idx & 15) * 8;
            cpasync16(&Bs[0][br][bc], Bg + (size_t)br * N + bc);
        }
        cpcommit();
    }

    int lrow = lane & 15;
    int lhi = (lane >> 4) & 1;
    int r = lane >> 2, c = lane & 3;

    for (int t = 0; t < T; t++) {
        int buf = t & 1;
        if (t + 1 < T) {
            int nb = 1 - buf;
            int k0g = (t + 1) * BK;
#pragma unroll
            for (int j = 0; j < 4; j++) {
                int idx = tid + 256 * j;
                int ar = idx >> 3, ac = (idx & 7) * 8;
                cpasync16(&As[nb][ar][ac], Ag + (size_t)ar * K + k0g + ac);
                int br = idx >> 4, bc = (idx & 15) * 8;
                cpasync16(&Bs[nb][br][bc], Bg + (size_t)(k0g + br) * N + bc);
            }
            cpcommit();
            cpwait1();
        } else {
            cpwait0();
        }
        __syncthreads();

        unsigned abase = (unsigned)__cvta_generic_to_shared(&As[buf][0][0]);
        unsigned bbase = (unsigned)__cvta_generic_to_shared(&Bs[buf][0][0]);
#pragma unroll
        for (int ks = 0; ks < 4; ks++) {
            int k0 = ks * 16;
            unsigned a[4][4], bq[4][2];
#pragma unroll
            for (int mi = 0; mi < 4; mi++) {
                unsigned ad = abase +
                    (((wm + mi * 16 + lrow) * A_STR) + k0 + lhi * 8) * 2;
                ldsm4(a[mi], ad);
            }
#pragma unroll
            for (int np = 0; np < 2; np++) {
                unsigned tmp[4];
                unsigned bd = bbase +
                    (((k0 + lrow) * B_STR) + wn + np * 16 + lhi * 8) * 2;
                ldsm4t(tmp, bd);
                bq[np * 2][0] = tmp[0]; bq[np * 2][1] = tmp[1];
                bq[np * 2 + 1][0] = tmp[2]; bq[np * 2 + 1][1] = tmp[3];
            }
#pragma unroll
            for (int mi = 0; mi < 4; mi++)
#pragma unroll
                for (int ni = 0; ni < 4; ni++) mma16h(acc[mi][ni], a[mi], bq[ni]);
        }
        __syncthreads();
    }

    int c2 = c * 2;
#pragma unroll
    for (int mi = 0; mi < 4; mi++) {
        int row0 = bm + wm + mi * 16 + r;
        int row1 = row0 + 8;
#pragma unroll
        for (int ni = 0; ni < 4; ni++) {
            int col = bn + wn + ni * 8 + c2;
            float v00 = acc[mi][ni][0], v01 = acc[mi][ni][1];
            float v10 = acc[mi][ni][2], v11 = acc[mi][ni][3];
            if (EPI == 0) {
                int h = col / 192;
                int f = col - h * 192;
                int which = f >> 6;
                int d = f & 63;
                __half* dst = (which == 0) ? oq : (which == 1) ? okk : ov;
                {
                    int b_ = row0 >> 11, s_ = row0 & 2047;
                    size_t base = (((size_t)(b_ * 16 + h) * S_SEQ + s_) * HD + d);
                    *(__half2*)&dst[base] = __floats2half2_rn(v00, v01);
                }
                {
                    int b_ = row1 >> 11, s_ = row1 & 2047;
                    size_t base = (((size_t)(b_ * 16 + h) * S_SEQ + s_) * HD + d);
                    *(__half2*)&dst[base] = __floats2half2_rn(v10, v11);
                }
            } else if (EPI == 1) {
                float2 bv = *(const float2*)&bias[col];
                float2 r0 = *(const float2*)&res[(size_t)row0 * N + col];
                float2 r1 = *(const float2*)&res[(size_t)row1 * N + col];
                float2 o0, o1;
                o0.x = v00 + bv.x + r0.x; o0.y = v01 + bv.y + r0.y;
                o1.x = v10 + bv.x + r1.x; o1.y = v11 + bv.y + r1.y;
                *(float2*)&outf[(size_t)row0 * N + col] = o0;
                *(float2*)&outf[(size_t)row1 * N + col] = o1;
            } else if (EPI == 3) {
                float2 bv = *(const float2*)&bias[col];
                float2 p0 = *(const float2*)&b2p[col];
                float2 p1 = *(const float2*)&b2p[D_EMB + col];
                float2 p2 = *(const float2*)&b2p[2 * D_EMB + col];
                float2 p3 = *(const float2*)&b2p[3 * D_EMB + col];
                float bx = bv.x + p0.x + p1.x + p2.x + p3.x;
                float by = bv.y + p0.y + p1.y + p2.y + p3.y;
                float2 r0 = *(const float2*)&res[(size_t)row0 * N + col];
                float2 r1 = *(const float2*)&res[(size_t)row1 * N + col];
                float2 o0, o1;
                o0.x = v00 + bx + r0.x; o0.y = v01 + by + r0.y;
                o1.x = v10 + bx + r1.x; o1.y = v11 + by + r1.y;
                *(float2*)&outf[(size_t)row0 * N + col] = o0;
                *(float2*)&outf[(size_t)row1 * N + col] = o1;
            } else {
                float2 bv = *(const float2*)&bias[col];
                *(__half2*)&outh[(size_t)row0 * N + col] =
                    __floats2half2_rn(geluf(v00 + bv.x), geluf(v01 + bv.y));
                *(__half2*)&outh[(size_t)row1 * N + col] =
                    __floats2half2_rn(geluf(v10 + bv.x), geluf(v11 + bv.y));
            }
        }
    }
}

// ---------------- fp16 tensor-core flash attention (R7-validated: 64 q-rows) ----------------
#define ATS 72
#define ATT_SMEM_BYTES ((64 * ATS + 2 * 64 * ATS + 2 * 64 * ATS + 64 * ATS) * 2)

__global__ void __launch_bounds__(128) attn_h(const __half* __restrict__ Qg,
                                              const __half* __restrict__ Kg,
                                              const __half* __restrict__ Vg,
                                              __half* __restrict__ Og) {
    extern __shared__ __half smh[];
    __half* Qs = smh;
    __half* Ks = Qs + 64 * ATS;
    __half* Vs = Ks + 2 * 64 * ATS;
    __half* Ps = Vs + 2 * 64 * ATS;

    int tid = threadIdx.x, lane = tid & 31, warp = tid >> 5;
    int r = lane >> 2, cq = lane & 3;
    int lrow = lane & 15, lhi = (lane >> 4) & 1;
    int q0 = blockIdx.x * 64, bh = blockIdx.y;
    const __half* qp = Qg + (size_t)bh * S_SEQ * HD;
    const __half* kp = Kg + (size_t)bh * S_SEQ * HD;
    const __half* vp = Vg + (size_t)bh * S_SEQ * HD;

#pragma unroll
    for (int j = 0; j < 4; j++) {
        int f = tid + 128 * j;
        int row = f >> 3, c8 = (f & 7) * 8;
        cpasync16(&Qs[row * ATS + c8], &qp[(size_t)(q0 + row) * HD + c8]);
        cpasync16(&Ks[row * ATS + c8], &kp[(size_t)row * HD + c8]);
        cpasync16(&Vs[row * ATS + c8], &vp[(size_t)row * HD + c8]);
    }
    cpcommit();

    unsigned qbase = (unsigned)__cvta_generic_to_shared(Qs);
    unsigned pbase = (unsigned)__cvta_generic_to_shared(Ps);
    int qrow = warp * 16 + r;
    int qtile = warp * 16;

    unsigned qa[4][4];
    float m0 = -1e30f, m1 = -1e30f, l0 = 0.f, l1 = 0.f;
    float oacc[8][4];
#pragma unroll
    for (int ni = 0; ni < 8; ni++)
#pragma unroll
        for (int q = 0; q < 4; q++) oacc[ni][q] = 0.f;

    const float scale = 0.125f;
    const int NT = S_SEQ / 64;
    for (int kt = 0; kt < NT; kt++) {
        int buf = kt & 1;
        if (kt + 1 < NT) {
            int nb = 1 - buf;
            const __half* kg = kp + (size_t)(kt + 1) * 64 * HD;
            const __half* vg = vp + (size_t)(kt + 1) * 64 * HD;
            __half* kd = Ks + nb * 64 * ATS;
            __half* vd = Vs + nb * 64 * ATS;
#pragma unroll
            for (int j = 0; j < 4; j++) {
                int f = tid + 128 * j;
                int row = f >> 3, c8 = (f & 7) * 8;
                cpasync16(&kd[row * ATS + c8], &kg[(size_t)row * HD + c8]);
                cpasync16(&vd[row * ATS + c8], &vg[(size_t)row * HD + c8]);
            }
            cpcommit();
            cpwait1();
        } else {
            cpwait0();
        }
        __syncthreads();
        if (kt == 0) {
#pragma unroll
            for (int kf = 0; kf < 4; kf++) {
                unsigned ad = qbase + ((qtile + lrow) * ATS + kf * 16 + lhi * 8) * 2;
                ldsm4(qa[kf], ad);
            }
        }
        unsigned kbase = (unsigned)__cvta_generic_to_shared(Ks + buf * 64 * ATS);
        unsigned vbase = (unsigned)__cvta_generic_to_shared(Vs + buf * 64 * ATS);

        float s[8][4];
#pragma unroll
        for (int ni = 0; ni < 8; ni++)
#pragma unroll
            for (int q = 0; q < 4; q++) s[ni][q] = 0.f;
#pragma unroll
        for (int kf = 0; kf < 4; kf++) {
#pragma unroll
            for (int ng = 0; ng < 4; ng++) {
                unsigned tmp[4];
                unsigned kd = kbase + ((ng * 16 + lrow) * ATS + kf * 16 + lhi * 8) * 2;
                ldsm4(tmp, kd);
                unsigned b0[2] = {tmp[0], tmp[2]};
                unsigned b1[2] = {tmp[1], tmp[3]};
                mma16h(s[ng * 2], qa[kf], b0);
                mma16h(s[ng * 2 + 1], qa[kf], b1);
            }
        }

        float rm0 = -1e30f, rm1 = -1e30f;
#pragma unroll
        for (int ni = 0; ni < 8; ni++) {
            s[ni][0] *= scale; s[ni][1] *= scale;
            s[ni][2] *= scale; s[ni][3] *= scale;
            rm0 = fmaxf(rm0, fmaxf(s[ni][0], s[ni][1]));
            rm1 = fmaxf(rm1, fmaxf(s[ni][2], s[ni][3]));
        }
        rm0 = fmaxf(rm0, __shfl_xor_sync(0xffffffffu, rm0, 1));
        rm0 = fmaxf(rm0, __shfl_xor_sync(0xffffffffu, rm0, 2));
        rm1 = fmaxf(rm1, __shfl_xor_sync(0xffffffffu, rm1, 1));
        rm1 = fmaxf(rm1, __shfl_xor_sync(0xffffffffu, rm1, 2));
        float mn0 = fmaxf(m0, rm0), mn1 = fmaxf(m1, rm1);
        float corr0 = __expf(m0 - mn0), corr1 = __expf(m1 - mn1);
        m0 = mn0; m1 = mn1;
        float rs0 = 0.f, rs1 = 0.f;
#pragma unroll
        for (int ni = 0; ni < 8; ni++) {
            float p0 = __expf(s[ni][0] - mn0);
            float p1 = __expf(s[ni][1] - mn0);
            float p2 = __expf(s[ni][2] - mn1);
            float p3 = __expf(s[ni][3] - mn1);
            rs0 += p0 + p1; rs1 += p2 + p3;
            *(__half2*)&Ps[qrow * ATS + ni * 8 + 2 * cq] = __floats2half2_rn(p0, p1);
            *(__half2*)&Ps[(qrow + 8) * ATS + ni * 8 + 2 * cq] = __floats2half2_rn(p2, p3);
        }
        rs0 += __shfl_xor_sync(0xffffffffu, rs0, 1);
        rs0 += __shfl_xor_sync(0xffffffffu, rs0, 2);
        rs1 += __shfl_xor_sync(0xffffffffu, rs1, 1);
        rs1 += __shfl_xor_sync(0xffffffffu, rs1, 2);
        l0 = l0 * corr0 + rs0;
        l1 = l1 * corr1 + rs1;
#pragma unroll
        for (int ni = 0; ni < 8; ni++) {
            oacc[ni][0] *= corr0; oacc[ni][1] *= corr0;
            oacc[ni][2] *= corr1; oacc[ni][3] *= corr1;
        }
        __syncwarp();

#pragma unroll
        for (int kc = 0; kc < 4; kc++) {
            unsigned pa[4];
            unsigned pd = pbase + ((qtile + lrow) * ATS + kc * 16 + lhi * 8) * 2;
            ldsm4(pa, pd);
#pragma unroll
            for (int ng = 0; ng < 4; ng++) {
                unsigned tmp[4];
                unsigned vd = vbase + ((kc * 16 + lrow) * ATS + ng * 16 + lhi * 8) * 2;
                ldsm4t(tmp, vd);
                unsigned b0[2] = {tmp[0], tmp[1]};
                unsigned b1[2] = {tmp[2], tmp[3]};
                mma16h(oacc[ng * 2], pa, b0);
                mma16h(oacc[ng * 2 + 1], pa, b1);
            }
        }
        __syncthreads();
    }

    int b_ = bh >> 4, h = bh & 15;
    float inv0 = 1.0f / l0, inv1 = 1.0f / l1;
    size_t t0 = ((size_t)b_ * S_SEQ + q0 + qrow) * D_EMB + h * HD;
    size_t t1 = ((size_t)b_ * S_SEQ + q0 + qrow + 8) * D_EMB + h * HD;
#pragma unroll
    for (int ni = 0; ni < 8; ni++) {
        int d = ni * 8 + 2 * cq;
        *(__half2*)&Og[t0 + d] = __floats2half2_rn(oacc[ni][0] * inv0, oacc[ni][1] * inv0);
        *(__half2*)&Og[t1 + d] = __floats2half2_rn(oacc[ni][2] * inv1, oacc[ni][3] * inv1);
    }
}

// ---------------- launch ----------------
extern "C" void kernel_launch(void* const* d_in, const int* in_sizes, int n_in,
                              void* d_out, int out_size) {
    const float* x = (const float*)d_in[0];
    const float* w_qkv = (const float*)d_in[1];
    const float* w_hproj = (const float*)d_in[2];
    const float* b_hproj = (const float*)d_in[3];
    const float* w_out = (const float*)d_in[4];
    const float* b_out = (const float*)d_in[5];
    const float* w_fc1 = (const float*)d_in[6];
    const float* b_fc1 = (const float*)d_in[7];
    const float* w_fc2 = (const float*)d_in[8];
    const float* b_fc2 = (const float*)d_in[9];
    const float* g1 = (const float*)d_in[10];
    const float* be1 = (const float*)d_in[11];
    const float* g2 = (const float*)d_in[12];
    const float* be2 = (const float*)d_in[13];
    float* out = (float*)d_out;

    __half *xnh, *qh, *kh, *vh, *oh, *hh, *W2h, *wqkvph, *wf1h, *wf2h;
    float *x1, *b2p;
    cudaGetSymbolAddress((void**)&xnh, g_xnh);
    cudaGetSymbolAddress((void**)&qh, g_qh);
    cudaGetSymbolAddress((void**)&kh, g_kh);
    cudaGetSymbolAddress((void**)&vh, g_vh);
    cudaGetSymbolAddress((void**)&oh, g_oh);
    cudaGetSymbolAddress((void**)&x1, g_x1);
    cudaGetSymbolAddress((void**)&hh, g_hh);
    cudaGetSymbolAddress((void**)&W2h, g_W2h);
    cudaGetSymbolAddress((void**)&b2p, g_b2p);
    cudaGetSymbolAddress((void**)&wqkvph, g_wqkvph);
    cudaGetSymbolAddress((void**)&wf1h, g_wf1h);
    cudaGetSymbolAddress((void**)&wf2h, g_wf2h);

    cudaFuncSetAttribute(attn_h, cudaFuncAttributeMaxDynamicSharedMemorySize,
                         ATT_SMEM_BYTES);
    cudaFuncSetAttribute(gemm_h<0>, cudaFuncAttributeMaxDynamicSharedMemorySize, GEMM_SMEM);
    cudaFuncSetAttribute(gemm_h<1>, cudaFuncAttributeMaxDynamicSharedMemorySize, GEMM_SMEM);
    cudaFuncSetAttribute(gemm_h<2>, cudaFuncAttributeMaxDynamicSharedMemorySize, GEMM_SMEM);
    cudaFuncSetAttribute(gemm_h<3>, cudaFuncAttributeMaxDynamicSharedMemorySize, GEMM_SMEM);

    // side stream + events (created once, outside capture, on the first
    // correctness call; reused identically on every call -> deterministic work)
    static cudaStream_t s2 = nullptr;
    static cudaEvent_t ev_fork = nullptr, ev_join = nullptr;
    if (s2 == nullptr) {
        cudaStreamCreateWithFlags(&s2, cudaStreamNonBlocking);
        cudaEventCreateWithFlags(&ev_fork, cudaEventDisableTiming);
        cudaEventCreateWithFlags(&ev_join, cudaEventDisableTiming);
    }

    // fork: weight prep that is NOT needed until the proj/MLP GEMMs runs on s2,
    // overlapping the LN1 -> QKV -> attention chain on the main stream.
    cudaEventRecord(ev_fork, 0);
    cudaStreamWaitEvent(s2, ev_fork, 0);
    fuse_w2_kernel<<<dim3(16, 16), 256, 0, s2>>>(w_hproj, w_out, W2h);
    bias2p_kernel<<<256, 256, 0, s2>>>(b_hproj, w_out, b2p);
    f2h2_kernel<<<8192, 256, 0, s2>>>(w_fc1, wf1h, w_fc2, wf2h, 1024 * 1024);
    cudaEventRecord(ev_join, s2);

    // main chain
    ln_kernel<<<T_TOK, 256>>>(x, g1, be1, xnh);
    repack_qkv_kernel<<<3072, 256>>>(w_qkv, wqkvph);
    // QKV: [4096,1024] x [1024,3072] -> per-head half q/k/v
    gemm_h<0><<<dim3(32, 24), 256, GEMM_SMEM>>>(xnh, wqkvph, T_TOK, 3072, D_EMB,
                                                nullptr, nullptr, nullptr, nullptr, nullptr,
                                                qh, kh, vh);
    // fp16 flash attention -> concat-head half
    attn_h<<<dim3(S_SEQ / 64, 32), 128, ATT_SMEM_BYTES>>>(qh, kh, vh, oh);

    // join: proj + MLP need W2h/b2p/wf1h/wf2h
    cudaStreamWaitEvent(0, ev_join, 0);
    // out projection + (bout + b2 partials) + residual -> x1 (f32)
    gemm_h<3><<<dim3(32, 8), 256, GEMM_SMEM>>>(oh, W2h, T_TOK, D_EMB, D_EMB,
                                               b_out, x, b2p, x1, nullptr,
                                               nullptr, nullptr, nullptr);
    // LN2
    ln_kernel<<<T_TOK, 256>>>(x1, g2, be2, xnh);
    // FC1 + bias + exact GELU -> half
    gemm_h<2><<<dim3(32, 32), 256, GEMM_SMEM>>>(xnh, wf1h, T_TOK, MLP_DIM, D_EMB,
                                                b_fc1, nullptr, nullptr, nullptr, hh,
                                                nullptr, nullptr, nullptr);
    // FC2 + bias + residual x1 -> out (f32)
    gemm_h<1><<<dim3(32, 8), 256, GEMM_SMEM>>>(hh, wf2h, T_TOK, D_EMB, MLP_DIM,
                                               b_fc2, x1, nullptr, out, nullptr,
                                               nullptr, nullptr, nullptr);
}